// round 2
// baseline (speedup 1.0000x reference)
#include <cuda_runtime.h>
#include <cstdint>
#include <math.h>

// Problem constants
#define B_  4
#define D_  1024
#define S_  2048
#define H_  16
#define HD_ 64
#define BS_ (B_*S_)

// ---------------------------------------------------------------------------
// Scratch (static device globals — no allocation allowed)
// ---------------------------------------------------------------------------
__device__ float g_pe [D_*S_];     //  8 MB  positional encoding [D][S]
__device__ float g_xt [BS_*(size_t)D_];   // 33.5 MB  x transposed+PE  [B,S,D]
__device__ float g_q  [BS_*(size_t)D_];   // Q in [B,H,S,hd]
__device__ float g_k  [BS_*(size_t)D_];   // K in [B,H,S,hd]
__device__ float g_v  [BS_*(size_t)D_];   // V in [B,H,S,hd]
__device__ float g_ctx[BS_*(size_t)D_];   // attention output [B,S,D]

// ---------------------------------------------------------------------------
// Helpers: tf32 convert + m16n8k8 tf32 mma
// ---------------------------------------------------------------------------
__device__ __forceinline__ uint32_t f2tf(float x) {
    uint32_t r;
    asm("cvt.rna.tf32.f32 %0, %1;" : "=r"(r) : "f"(x));
    return r;
}

__device__ __forceinline__ void mma_tf32(float* c, const uint32_t* a, const uint32_t* b) {
    asm volatile(
        "mma.sync.aligned.m16n8k8.row.col.f32.tf32.tf32.f32 "
        "{%0,%1,%2,%3}, {%4,%5,%6,%7}, {%8,%9}, {%0,%1,%2,%3};\n"
        : "+f"(c[0]), "+f"(c[1]), "+f"(c[2]), "+f"(c[3])
        : "r"(a[0]), "r"(a[1]), "r"(a[2]), "r"(a[3]), "r"(b[0]), "r"(b[1]));
}

// ---------------------------------------------------------------------------
// 1) Positional encoding table  pe[d][s]
//    even d: sin(s * exp(-d * ln(10000)/D)); odd d: cos with (d-1)
//    Double-precision trig: angles reach ~2047, need exact range reduction so
//    sin/cos of the *same fp32 angle* JAX computes match to fp32 rounding.
// ---------------------------------------------------------------------------
__global__ void pe_kernel() {
    int idx = blockIdx.x * blockDim.x + threadIdx.x;
    if (idx >= D_ * S_) return;
    int d = idx / S_;
    int s = idx - d * S_;
    double freq_d = exp((double)(d & ~1) * (-9.210340371976184 / (double)D_)); // ln(10000)
    float  freq   = (float)freq_d;               // match JAX fp32 denom
    float  ang    = (float)s * freq;             // fp32 angle, same as JAX
    float  val    = (d & 1) ? (float)cos((double)ang) : (float)sin((double)ang);
    g_pe[idx] = val;
}

// ---------------------------------------------------------------------------
// 2) x[B,D,S] + pe[D,S]  ->  xt[B,S,D]   (tiled transpose, PE added on the
//    coalesced read side since pe has the same [D,S] layout as x)
// ---------------------------------------------------------------------------
__global__ void addpe_transpose(const float* __restrict__ x) {
    __shared__ float tile[32][33];
    int b  = blockIdx.z;
    int d0 = blockIdx.y * 32;
    int s0 = blockIdx.x * 32;
    int tx = threadIdx.x, ty = threadIdx.y;  // (32, 8)
#pragma unroll
    for (int j = 0; j < 4; j++) {
        int d = d0 + ty + j * 8;
        tile[ty + j * 8][tx] = x[((size_t)b * D_ + d) * S_ + s0 + tx]
                             + g_pe[(size_t)d * S_ + s0 + tx];
    }
    __syncthreads();
#pragma unroll
    for (int j = 0; j < 4; j++) {
        int s = s0 + ty + j * 8;
        g_xt[((size_t)b * S_ + s) * D_ + d0 + tx] = tile[tx][ty + j * 8];
    }
}

// ---------------------------------------------------------------------------
// 3/5) TF32 GEMM:  C[M,N] = A[M,K] @ W[N,K]^T + bias
//      BM=128 BN=128 BK=32, 256 threads (8 warps, 4x2), warp tile 32x64.
//      Smem stored k-major [k][m] with row stride 132 (132 % 32 == 4) so the
//      mma fragment LDS pattern (4k + m) hits 32 distinct banks.
// MODE 1: scatter to [B,H,S,hd] (Q/K/V).   MODE 2: transpose to [B,D,S] (out).
// ---------------------------------------------------------------------------
template <int MODE>
__global__ void __launch_bounds__(256)
gemm_tf32(const float* __restrict__ A, const float* __restrict__ W,
          const float* __restrict__ bias, float* __restrict__ C,
          int M, int N, int K) {
    __shared__ float As[32][132];
    __shared__ float Bs[32][132];

    int t    = threadIdx.x;
    int wid  = t >> 5, lane = t & 31;
    int lm   = lane >> 2, lk = lane & 3;
    int wm   = (wid >> 1) * 32;   // warp M offset (0..96)
    int wn   = (wid & 1) * 64;    // warp N offset (0/64)
    int bm   = blockIdx.y * 128;
    int bn   = blockIdx.x * 128;

    float c[2][8][4];
#pragma unroll
    for (int mt = 0; mt < 2; mt++)
#pragma unroll
        for (int nt = 0; nt < 8; nt++)
#pragma unroll
            for (int i = 0; i < 4; i++) c[mt][nt][i] = 0.f;

    int arow = t >> 3;            // 0..31
    int ak4  = (t & 7) * 4;       // 0..28
    const float* Aptr = A + (size_t)(bm + arow) * K + ak4;
    const float* Wptr = W + (size_t)(bn + arow) * K + ak4;

    for (int k0 = 0; k0 < K; k0 += 32) {
#pragma unroll
        for (int p = 0; p < 4; p++) {
            float4 va = *(const float4*)(Aptr + (size_t)(p * 32) * K + k0);
            int m = arow + p * 32;
            As[ak4 + 0][m] = va.x; As[ak4 + 1][m] = va.y;
            As[ak4 + 2][m] = va.z; As[ak4 + 3][m] = va.w;
            float4 vb = *(const float4*)(Wptr + (size_t)(p * 32) * K + k0);
            Bs[ak4 + 0][m] = vb.x; Bs[ak4 + 1][m] = vb.y;
            Bs[ak4 + 2][m] = vb.z; Bs[ak4 + 3][m] = vb.w;
        }
        __syncthreads();

#pragma unroll
        for (int k8 = 0; k8 < 4; k8++) {
            int kb = k8 * 8;
            uint32_t a[2][4];
#pragma unroll
            for (int mt = 0; mt < 2; mt++) {
                int r = wm + mt * 16 + lm;
                a[mt][0] = f2tf(As[kb + lk    ][r    ]);
                a[mt][1] = f2tf(As[kb + lk    ][r + 8]);
                a[mt][2] = f2tf(As[kb + lk + 4][r    ]);
                a[mt][3] = f2tf(As[kb + lk + 4][r + 8]);
            }
            uint32_t bf[8][2];
#pragma unroll
            for (int nt = 0; nt < 8; nt++) {
                int cn = wn + nt * 8 + lm;
                bf[nt][0] = f2tf(Bs[kb + lk    ][cn]);
                bf[nt][1] = f2tf(Bs[kb + lk + 4][cn]);
            }
#pragma unroll
            for (int mt = 0; mt < 2; mt++)
#pragma unroll
                for (int nt = 0; nt < 8; nt++)
                    mma_tf32(c[mt][nt], a[mt], bf[nt]);
        }
        __syncthreads();
    }

    // Epilogue
#pragma unroll
    for (int mt = 0; mt < 2; mt++) {
        int r0 = bm + wm + mt * 16 + lm;   // rows r0, r0+8
#pragma unroll
        for (int nt = 0; nt < 8; nt++) {
            int col = bn + wn + nt * 8 + 2 * lk;   // cols col, col+1
            float b0 = bias[col], b1 = bias[col + 1];
            float v00 = c[mt][nt][0] + b0, v01 = c[mt][nt][1] + b1;  // row r0
            float v10 = c[mt][nt][2] + b0, v11 = c[mt][nt][3] + b1;  // row r0+8
            if (MODE == 1) {
                // scatter to [B,H,S,hd]; col even -> hd,hd+1 contiguous
                int b  = r0 / S_;
                int h  = col >> 6;
                int hd = col & 63;
                int s  = r0 - b * S_;
                float2* p0 = (float2*)&C[(((size_t)(b * H_ + h)) * S_ + s    ) * HD_ + hd];
                float2* p1 = (float2*)&C[(((size_t)(b * H_ + h)) * S_ + s + 8) * HD_ + hd];
                *p0 = make_float2(v00, v01);
                *p1 = make_float2(v10, v11);
            } else {
                // transpose to [B,D,S]
                int b = r0 / S_;
                int s = r0 - b * S_;
                C[((size_t)b * D_ + col    ) * S_ + s    ] = v00;
                C[((size_t)b * D_ + col + 1) * S_ + s    ] = v01;
                C[((size_t)b * D_ + col    ) * S_ + s + 8] = v10;
                C[((size_t)b * D_ + col + 1) * S_ + s + 8] = v11;
            }
        }
    }
}

// ---------------------------------------------------------------------------
// 4) Flash attention.  Grid (S/64, B*H), 128 threads (4 warps x 16 q-rows).
//    64-key tiles; S = Q K^T via tf32 mma; online softmax on C fragments
//    (quad shuffles); P re-fragmented through per-warp padded smem; O += P V.
// ---------------------------------------------------------------------------
#define QS_STRIDE 68   // 68 % 32 == 4 -> conflict-free fragment LDS
#define PS_STRIDE 24   // (24k + m) % 32 distinct over the fragment pattern
#define ATTN_SMEM_FLOATS (3 * 64 * QS_STRIDE + 4 * 64 * PS_STRIDE)
#define ATTN_SMEM_BYTES  (ATTN_SMEM_FLOATS * (int)sizeof(float))

__global__ void __launch_bounds__(128)
flash_attn() {
    extern __shared__ float sm[];
    float* Qs = sm;                        // [64 d][68]  (q rows, pre-scaled)
    float* Ks = Qs + 64 * QS_STRIDE;       // [64 d][68]  (keys)
    float* Vs = Ks + 64 * QS_STRIDE;       // [64 key][68] (d)
    float* Ps = Vs + 64 * QS_STRIDE;       // [4 warp][64 key][24]

    int t = threadIdx.x, w = t >> 5, lane = t & 31;
    int lm = lane >> 2, lk = lane & 3;
    int bh = blockIdx.y;
    int qb = blockIdx.x * 64;
    size_t base = (size_t)bh * S_ * HD_;

    // Load Q tile (scaled by 1/sqrt(hd) = 0.125)
    for (int i = t; i < 64 * 64; i += 128) {
        int r = i >> 6, d = i & 63;
        Qs[d * QS_STRIDE + r] = g_q[base + (size_t)(qb + r) * HD_ + d] * 0.125f;
    }

    float o[8][4];
#pragma unroll
    for (int nt = 0; nt < 8; nt++)
#pragma unroll
        for (int i = 0; i < 4; i++) o[nt][i] = 0.f;
    float m0 = -INFINITY, m1 = -INFINITY, l0 = 0.f, l1 = 0.f;
    float* Pw = Ps + w * 64 * PS_STRIDE;

    for (int kt = 0; kt < S_; kt += 64) {
        __syncthreads();   // previous-iter consumers done (also covers Q load)
        for (int i = t; i < 64 * 64; i += 128) {
            int r = i >> 6, d = i & 63;
            float kv = g_k[base + (size_t)(kt + r) * HD_ + d];
            float vv = g_v[base + (size_t)(kt + r) * HD_ + d];
            Ks[d * QS_STRIDE + r] = kv;
            Vs[r * QS_STRIDE + d] = vv;
        }
        __syncthreads();

        // S = Q K^T  (warp: 16 q-rows x 64 keys)
        float sacc[8][4];
#pragma unroll
        for (int nt = 0; nt < 8; nt++)
#pragma unroll
            for (int i = 0; i < 4; i++) sacc[nt][i] = 0.f;

#pragma unroll
        for (int k8 = 0; k8 < 8; k8++) {
            int kb = k8 * 8;
            int r  = w * 16 + lm;
            uint32_t a[4];
            a[0] = f2tf(Qs[(kb + lk    ) * QS_STRIDE + r    ]);
            a[1] = f2tf(Qs[(kb + lk    ) * QS_STRIDE + r + 8]);
            a[2] = f2tf(Qs[(kb + lk + 4) * QS_STRIDE + r    ]);
            a[3] = f2tf(Qs[(kb + lk + 4) * QS_STRIDE + r + 8]);
#pragma unroll
            for (int nt = 0; nt < 8; nt++) {
                uint32_t bb[2];
                bb[0] = f2tf(Ks[(kb + lk    ) * QS_STRIDE + nt * 8 + lm]);
                bb[1] = f2tf(Ks[(kb + lk + 4) * QS_STRIDE + nt * 8 + lm]);
                mma_tf32(sacc[nt], a, bb);
            }
        }

        // Online softmax (rows lm and lm+8; 4 lanes per row -> xor 1,2)
        float mx0 = -INFINITY, mx1 = -INFINITY;
#pragma unroll
        for (int nt = 0; nt < 8; nt++) {
            mx0 = fmaxf(mx0, fmaxf(sacc[nt][0], sacc[nt][1]));
            mx1 = fmaxf(mx1, fmaxf(sacc[nt][2], sacc[nt][3]));
        }
        mx0 = fmaxf(mx0, __shfl_xor_sync(0xffffffffu, mx0, 1));
        mx0 = fmaxf(mx0, __shfl_xor_sync(0xffffffffu, mx0, 2));
        mx1 = fmaxf(mx1, __shfl_xor_sync(0xffffffffu, mx1, 1));
        mx1 = fmaxf(mx1, __shfl_xor_sync(0xffffffffu, mx1, 2));

        float nm0 = fmaxf(m0, mx0), nm1 = fmaxf(m1, mx1);
        float sc0 = __expf(m0 - nm0), sc1 = __expf(m1 - nm1);
        float rs0 = 0.f, rs1 = 0.f;
#pragma unroll
        for (int nt = 0; nt < 8; nt++) {
            sacc[nt][0] = __expf(sacc[nt][0] - nm0);
            sacc[nt][1] = __expf(sacc[nt][1] - nm0);
            sacc[nt][2] = __expf(sacc[nt][2] - nm1);
            sacc[nt][3] = __expf(sacc[nt][3] - nm1);
            rs0 += sacc[nt][0] + sacc[nt][1];
            rs1 += sacc[nt][2] + sacc[nt][3];
        }
        rs0 += __shfl_xor_sync(0xffffffffu, rs0, 1);
        rs0 += __shfl_xor_sync(0xffffffffu, rs0, 2);
        rs1 += __shfl_xor_sync(0xffffffffu, rs1, 1);
        rs1 += __shfl_xor_sync(0xffffffffu, rs1, 2);

        l0 = l0 * sc0 + rs0;  l1 = l1 * sc1 + rs1;
        m0 = nm0;             m1 = nm1;
#pragma unroll
        for (int nt = 0; nt < 8; nt++) {
            o[nt][0] *= sc0; o[nt][1] *= sc0;
            o[nt][2] *= sc1; o[nt][3] *= sc1;
        }

        // P -> per-warp smem [key][qrow] for re-fragmentation
#pragma unroll
        for (int nt = 0; nt < 8; nt++) {
            int kc = nt * 8 + 2 * lk;
            Pw[(kc    ) * PS_STRIDE + lm    ] = sacc[nt][0];
            Pw[(kc + 1) * PS_STRIDE + lm    ] = sacc[nt][1];
            Pw[(kc    ) * PS_STRIDE + lm + 8] = sacc[nt][2];
            Pw[(kc + 1) * PS_STRIDE + lm + 8] = sacc[nt][3];
        }
        __syncwarp();

        // O += P V
#pragma unroll
        for (int k8 = 0; k8 < 8; k8++) {
            int kb = k8 * 8;
            uint32_t a[4];
            a[0] = f2tf(Pw[(kb + lk    ) * PS_STRIDE + lm    ]);
            a[1] = f2tf(Pw[(kb + lk    ) * PS_STRIDE + lm + 8]);
            a[2] = f2tf(Pw[(kb + lk + 4) * PS_STRIDE + lm    ]);
            a[3] = f2tf(Pw[(kb + lk + 4) * PS_STRIDE + lm + 8]);
#pragma unroll
            for (int nt = 0; nt < 8; nt++) {
                uint32_t bb[2];
                bb[0] = f2tf(Vs[(kb + lk    ) * QS_STRIDE + nt * 8 + lm]);
                bb[1] = f2tf(Vs[(kb + lk + 4) * QS_STRIDE + nt * 8 + lm]);
                mma_tf32(o[nt], a, bb);
            }
        }
        __syncwarp();
    }

    // Epilogue: normalize, write ctx[B,S,D] at head h's columns
    float inv0 = 1.f / l0, inv1 = 1.f / l1;
    int b = bh / H_, h = bh - b * H_;
    int srow = qb + w * 16 + lm;
#pragma unroll
    for (int nt = 0; nt < 8; nt++) {
        int col = h * HD_ + nt * 8 + 2 * lk;
        float2* p0 = (float2*)&g_ctx[((size_t)b * S_ + srow    ) * D_ + col];
        float2* p1 = (float2*)&g_ctx[((size_t)b * S_ + srow + 8) * D_ + col];
        *p0 = make_float2(o[nt][0] * inv0, o[nt][1] * inv0);
        *p1 = make_float2(o[nt][2] * inv1, o[nt][3] * inv1);
    }
}

// ---------------------------------------------------------------------------
// Launch
// ---------------------------------------------------------------------------
extern "C" void kernel_launch(void* const* d_in, const int* in_sizes, int n_in,
                              void* d_out, int out_size) {
    (void)in_sizes; (void)n_in; (void)out_size;
    const float* x  = (const float*)d_in[0];
    const float* Wq = (const float*)d_in[1];
    const float* bq = (const float*)d_in[2];
    const float* Wk = (const float*)d_in[3];
    const float* bk = (const float*)d_in[4];
    const float* Wv = (const float*)d_in[5];
    const float* bv = (const float*)d_in[6];
    const float* Wo = (const float*)d_in[7];
    const float* bo = (const float*)d_in[8];
    float* out = (float*)d_out;

    float *xt, *q, *k, *v, *ctx;
    cudaGetSymbolAddress((void**)&xt,  g_xt);
    cudaGetSymbolAddress((void**)&q,   g_q);
    cudaGetSymbolAddress((void**)&k,   g_k);
    cudaGetSymbolAddress((void**)&v,   g_v);
    cudaGetSymbolAddress((void**)&ctx, g_ctx);

    static bool attr_set = false;
    if (!attr_set) {
        cudaFuncSetAttribute(flash_attn,
                             cudaFuncAttributeMaxDynamicSharedMemorySize,
                             ATTN_SMEM_BYTES);
        attr_set = true;
    }

    // 1) PE table
    pe_kernel<<<(D_ * S_ + 255) / 256, 256>>>();
    // 2) x + PE, transpose to [B,S,D]
    addpe_transpose<<<dim3(S_ / 32, D_ / 32, B_), dim3(32, 8)>>>(x);
    // 3) Q/K/V projections -> [B,H,S,hd]
    dim3 ggrid(D_ / 128, BS_ / 128);
    gemm_tf32<1><<<ggrid, 256>>>(xt, Wq, bq, q, BS_, D_, D_);
    gemm_tf32<1><<<ggrid, 256>>>(xt, Wk, bk, k, BS_, D_, D_);
    gemm_tf32<1><<<ggrid, 256>>>(xt, Wv, bv, v, BS_, D_, D_);
    // 4) attention -> ctx[B,S,D]
    flash_attn<<<dim3(S_ / 64, B_ * H_), 128, ATTN_SMEM_BYTES>>>();
    // 5) output projection, transposed epilogue -> [B,D,S]
    gemm_tf32<2><<<ggrid, 256>>>(ctx, Wo, bo, out, BS_, D_, D_);
}

// round 3
// speedup vs baseline: 1.6879x; 1.6879x over previous
#include <cuda_runtime.h>
#include <cstdint>
#include <math.h>

// Problem constants
#define B_  4
#define D_  1024
#define S_  2048
#define H_  16
#define HD_ 64
#define BS_ (B_*S_)

// ---------------------------------------------------------------------------
// Scratch (static device globals — no allocation allowed)
// ---------------------------------------------------------------------------
__device__ float g_pe [D_*S_];            //  8 MB  positional encoding [D][S]
__device__ float g_xt [BS_*(size_t)D_];   // 33.5 MB  x transposed+PE  [B,S,D]
__device__ float g_q  [BS_*(size_t)D_];   // Q in [B,H,S,hd]
__device__ float g_k  [BS_*(size_t)D_];   // K in [B,H,S,hd]
__device__ float g_v  [BS_*(size_t)D_];   // V in [B,H,S,hd]
__device__ float g_ctx[BS_*(size_t)D_];   // attention output [B,S,D]

// ---------------------------------------------------------------------------
// Helpers
// ---------------------------------------------------------------------------
__device__ __forceinline__ uint32_t f2tf(float x) {
    uint32_t r;
    asm("cvt.rna.tf32.f32 %0, %1;" : "=r"(r) : "f"(x));
    return r;
}

__device__ __forceinline__ void mma_tf32(float* c, const uint32_t* a, const uint32_t* b) {
    asm volatile(
        "mma.sync.aligned.m16n8k8.row.col.f32.tf32.tf32.f32 "
        "{%0,%1,%2,%3}, {%4,%5,%6,%7}, {%8,%9}, {%0,%1,%2,%3};\n"
        : "+f"(c[0]), "+f"(c[1]), "+f"(c[2]), "+f"(c[3])
        : "r"(a[0]), "r"(a[1]), "r"(a[2]), "r"(a[3]), "r"(b[0]), "r"(b[1]));
}

__device__ __forceinline__ uint32_t s2u(const void* p) {
    return (uint32_t)__cvta_generic_to_shared(p);
}

__device__ __forceinline__ void cpasync16(uint32_t dst, const void* src) {
    asm volatile("cp.async.ca.shared.global [%0], [%1], 16;\n" :: "r"(dst), "l"(src));
}
__device__ __forceinline__ void cp_commit() {
    asm volatile("cp.async.commit_group;\n");
}
__device__ __forceinline__ void cp_wait0() {
    asm volatile("cp.async.wait_group 0;\n");
}

// ---------------------------------------------------------------------------
// 1) Positional encoding table  pe[d][s]  (double trig for exact fp32 match)
// ---------------------------------------------------------------------------
__global__ void pe_kernel() {
    int idx = blockIdx.x * blockDim.x + threadIdx.x;
    if (idx >= D_ * S_) return;
    int d = idx / S_;
    int s = idx - d * S_;
    double freq_d = exp((double)(d & ~1) * (-9.210340371976184 / (double)D_));
    float  freq   = (float)freq_d;
    float  ang    = (float)s * freq;
    float  val    = (d & 1) ? (float)cos((double)ang) : (float)sin((double)ang);
    g_pe[idx] = val;
}

// ---------------------------------------------------------------------------
// 2) x[B,D,S] + pe[D,S]  ->  xt[B,S,D]
// ---------------------------------------------------------------------------
__global__ void addpe_transpose(const float* __restrict__ x) {
    __shared__ float tile[32][33];
    int b  = blockIdx.z;
    int d0 = blockIdx.y * 32;
    int s0 = blockIdx.x * 32;
    int tx = threadIdx.x, ty = threadIdx.y;  // (32, 8)
#pragma unroll
    for (int j = 0; j < 4; j++) {
        int d = d0 + ty + j * 8;
        tile[ty + j * 8][tx] = x[((size_t)b * D_ + d) * S_ + s0 + tx]
                             + g_pe[(size_t)d * S_ + s0 + tx];
    }
    __syncthreads();
#pragma unroll
    for (int j = 0; j < 4; j++) {
        int s = s0 + ty + j * 8;
        g_xt[((size_t)b * S_ + s) * D_ + d0 + tx] = tile[tx][ty + j * 8];
    }
}

// ---------------------------------------------------------------------------
// 3/5) TF32 GEMM, cp.async double-buffered.
//      C[M,N] = A[M,K] @ W[N,K]^T + bias.  BM=BN=128, BK=32, 256 thr, 8 warps.
//      Smem natural [row][k] layout, stride 36 (36%32==4 -> conflict-free
//      fragment LDS: addr%32 = 4*lm + lk).  Both tiles k-contiguous in
//      global -> direct cp.async, no register staging, no STS transpose.
// MODE 1: scatter to [B,H,S,hd].   MODE 2: transpose to [B,D,S].
// ---------------------------------------------------------------------------
#define GST 36
#define GEMM_SMEM_BYTES (2 * 2 * 128 * GST * 4)   // 73728

template <int MODE>
__global__ void __launch_bounds__(256, 2)
gemm_tf32(const float* __restrict__ A, const float* __restrict__ W,
          const float* __restrict__ bias, float* __restrict__ C,
          int M, int N, int K) {
    extern __shared__ float sm[];
    float* As = sm;                    // [2][128][36]
    float* Bs = sm + 2 * 128 * GST;    // [2][128][36]
    uint32_t sA = s2u(As), sB = s2u(Bs);

    int t    = threadIdx.x;
    int wid  = t >> 5, lane = t & 31;
    int lm   = lane >> 2, lk = lane & 3;
    int wm   = (wid >> 1) * 32;
    int wn   = (wid & 1) * 64;
    int bm   = blockIdx.y * 128;
    int bn   = blockIdx.x * 128;

    float c[2][8][4];
#pragma unroll
    for (int mt = 0; mt < 2; mt++)
#pragma unroll
        for (int nt = 0; nt < 8; nt++)
#pragma unroll
            for (int i = 0; i < 4; i++) c[mt][nt][i] = 0.f;

    int rowg = t >> 3;        // 0..31
    int chk  = t & 7;         // 0..7  (8 x 16B chunks per 32-float row)

    auto issue = [&](int k0, int p) {
#pragma unroll
        for (int i = 0; i < 4; i++) {
            int r = rowg + i * 32;
            cpasync16(sA + (((p * 128 + r) * GST) + chk * 4) * 4,
                      A + (size_t)(bm + r) * K + k0 + chk * 4);
            cpasync16(sB + (((p * 128 + r) * GST) + chk * 4) * 4,
                      W + (size_t)(bn + r) * K + k0 + chk * 4);
        }
        cp_commit();
    };

    int ntiles = K >> 5;
    issue(0, 0);

    for (int it = 0; it < ntiles; it++) {
        int p = it & 1;
        cp_wait0();
        __syncthreads();
        if (it + 1 < ntiles) issue((it + 1) << 5, 1 - p);

        const float* Ab = As + p * 128 * GST;
        const float* Bb = Bs + p * 128 * GST;
#pragma unroll
        for (int k8 = 0; k8 < 4; k8++) {
            int kb = k8 * 8;
            uint32_t a[2][4];
#pragma unroll
            for (int mt = 0; mt < 2; mt++) {
                int r = wm + mt * 16 + lm;
                a[mt][0] = f2tf(Ab[(size_t)(r    ) * GST + kb + lk    ]);
                a[mt][1] = f2tf(Ab[(size_t)(r + 8) * GST + kb + lk    ]);
                a[mt][2] = f2tf(Ab[(size_t)(r    ) * GST + kb + lk + 4]);
                a[mt][3] = f2tf(Ab[(size_t)(r + 8) * GST + kb + lk + 4]);
            }
            uint32_t bf[8][2];
#pragma unroll
            for (int nt = 0; nt < 8; nt++) {
                int cn = wn + nt * 8 + lm;
                bf[nt][0] = f2tf(Bb[(size_t)cn * GST + kb + lk    ]);
                bf[nt][1] = f2tf(Bb[(size_t)cn * GST + kb + lk + 4]);
            }
#pragma unroll
            for (int mt = 0; mt < 2; mt++)
#pragma unroll
                for (int nt = 0; nt < 8; nt++)
                    mma_tf32(c[mt][nt], a[mt], bf[nt]);
        }
        __syncthreads();
    }

    // Epilogue
#pragma unroll
    for (int mt = 0; mt < 2; mt++) {
        int r0 = bm + wm + mt * 16 + lm;
#pragma unroll
        for (int nt = 0; nt < 8; nt++) {
            int col = bn + wn + nt * 8 + 2 * lk;
            float b0 = bias[col], b1 = bias[col + 1];
            float v00 = c[mt][nt][0] + b0, v01 = c[mt][nt][1] + b1;
            float v10 = c[mt][nt][2] + b0, v11 = c[mt][nt][3] + b1;
            if (MODE == 1) {
                int b  = r0 / S_;
                int h  = col >> 6;
                int hd = col & 63;
                int s  = r0 - b * S_;
                float2* p0 = (float2*)&C[(((size_t)(b * H_ + h)) * S_ + s    ) * HD_ + hd];
                float2* p1 = (float2*)&C[(((size_t)(b * H_ + h)) * S_ + s + 8) * HD_ + hd];
                *p0 = make_float2(v00, v01);
                *p1 = make_float2(v10, v11);
            } else {
                int b = r0 / S_;
                int s = r0 - b * S_;
                C[((size_t)b * D_ + col    ) * S_ + s    ] = v00;
                C[((size_t)b * D_ + col + 1) * S_ + s    ] = v01;
                C[((size_t)b * D_ + col    ) * S_ + s + 8] = v10;
                C[((size_t)b * D_ + col + 1) * S_ + s + 8] = v11;
            }
        }
    }
}

// ---------------------------------------------------------------------------
// 4) Flash attention.  Grid (S/128, B*H), 256 threads (8 warps x 16 q-rows).
//    64-key tiles, cp.async double-buffered K/V (natural [key][d] layout,
//    K stride 68, V stride 72 -> both fragment patterns conflict-free).
//    Q pre-scaled + pre-converted to tf32 bits in smem.
//    P re-fragmentation via quad shuffles (no smem round-trip).
// ---------------------------------------------------------------------------
#define QST 132   // 132%32==4
#define KST 68    //  68%32==4 : K b-frag addr = 68*(nt*8+lm) + lk -> 4lm+lk
#define VST 72    //  72%32==8 : V b-frag addr = 72*(kb+lk) + nt*8+lm -> 8lk+lm
#define ATTN_SMEM_BYTES ((64*QST + 2*64*KST + 2*64*VST) * 4)   // 105472

__global__ void __launch_bounds__(256, 2)
flash_attn() {
    extern __shared__ float sm[];
    uint32_t* Qs = (uint32_t*)sm;          // [64 d][132]  (tf32 bits, scaled)
    float* Ks = sm + 64 * QST;             // [2][64 key][68]
    float* Vs = Ks + 2 * 64 * KST;         // [2][64 key][72]
    uint32_t sK = s2u(Ks), sV = s2u(Vs);

    int t = threadIdx.x, w = t >> 5, lane = t & 31;
    int lm = lane >> 2, lk = lane & 3;
    int bh = blockIdx.y;
    int qb = blockIdx.x * 128;
    size_t base = (size_t)bh * S_ * HD_;

    int rowg = t >> 4;   // 0..15
    int chk  = t & 15;   // 0..15 (16 x 16B chunks per 64-float row)

    auto issue = [&](int kt, int p) {
#pragma unroll
        for (int i = 0; i < 4; i++) {
            int r = rowg + i * 16;
            const float* src = g_k + base + (size_t)(kt + r) * HD_ + chk * 4;
            cpasync16(sK + (((p * 64 + r) * KST) + chk * 4) * 4, src);
            const float* srv = g_v + base + (size_t)(kt + r) * HD_ + chk * 4;
            cpasync16(sV + (((p * 64 + r) * VST) + chk * 4) * 4, srv);
        }
        cp_commit();
    };

    // Load Q tile: 128 rows x 64 d, scale by 0.125, cvt, store [d][row]
#pragma unroll
    for (int i = 0; i < 8; i++) {
        int r = rowg + i * 16;
        float4 v = *(const float4*)(g_q + base + (size_t)(qb + r) * HD_ + chk * 4);
        Qs[(chk * 4 + 0) * QST + r] = f2tf(v.x * 0.125f);
        Qs[(chk * 4 + 1) * QST + r] = f2tf(v.y * 0.125f);
        Qs[(chk * 4 + 2) * QST + r] = f2tf(v.z * 0.125f);
        Qs[(chk * 4 + 3) * QST + r] = f2tf(v.w * 0.125f);
    }

    issue(0, 0);

    float o[8][4];
#pragma unroll
    for (int nt = 0; nt < 8; nt++)
#pragma unroll
        for (int i = 0; i < 4; i++) o[nt][i] = 0.f;
    float m0 = -INFINITY, m1 = -INFINITY, l0 = 0.f, l1 = 0.f;

    const int NT = S_ / 64;
    for (int it = 0; it < NT; it++) {
        int p = it & 1;
        cp_wait0();
        __syncthreads();   // tile p ready; everyone done with compute(it-1)
        if (it + 1 < NT) issue((it + 1) * 64, 1 - p);

        const float* Kb = Ks + p * 64 * KST;
        const float* Vb = Vs + p * 64 * VST;

        // S = Q K^T
        float sacc[8][4];
#pragma unroll
        for (int nt = 0; nt < 8; nt++)
#pragma unroll
            for (int i = 0; i < 4; i++) sacc[nt][i] = 0.f;

        int r = w * 16 + lm;
#pragma unroll
        for (int k8 = 0; k8 < 8; k8++) {
            int kb = k8 * 8;
            uint32_t a[4];
            a[0] = Qs[(kb + lk    ) * QST + r    ];
            a[1] = Qs[(kb + lk    ) * QST + r + 8];
            a[2] = Qs[(kb + lk + 4) * QST + r    ];
            a[3] = Qs[(kb + lk + 4) * QST + r + 8];
#pragma unroll
            for (int nt = 0; nt < 8; nt++) {
                uint32_t bb[2];
                bb[0] = f2tf(Kb[(size_t)(nt * 8 + lm) * KST + kb + lk    ]);
                bb[1] = f2tf(Kb[(size_t)(nt * 8 + lm) * KST + kb + lk + 4]);
                mma_tf32(sacc[nt], a, bb);
            }
        }

        // Online softmax (rows lm, lm+8; 4 lanes per row -> xor 1,2)
        float mx0 = -INFINITY, mx1 = -INFINITY;
#pragma unroll
        for (int nt = 0; nt < 8; nt++) {
            mx0 = fmaxf(mx0, fmaxf(sacc[nt][0], sacc[nt][1]));
            mx1 = fmaxf(mx1, fmaxf(sacc[nt][2], sacc[nt][3]));
        }
        mx0 = fmaxf(mx0, __shfl_xor_sync(0xffffffffu, mx0, 1));
        mx0 = fmaxf(mx0, __shfl_xor_sync(0xffffffffu, mx0, 2));
        mx1 = fmaxf(mx1, __shfl_xor_sync(0xffffffffu, mx1, 1));
        mx1 = fmaxf(mx1, __shfl_xor_sync(0xffffffffu, mx1, 2));

        float nm0 = fmaxf(m0, mx0), nm1 = fmaxf(m1, mx1);
        float sc0 = __expf(m0 - nm0), sc1 = __expf(m1 - nm1);
        float rs0 = 0.f, rs1 = 0.f;
#pragma unroll
        for (int nt = 0; nt < 8; nt++) {
            sacc[nt][0] = __expf(sacc[nt][0] - nm0);
            sacc[nt][1] = __expf(sacc[nt][1] - nm0);
            sacc[nt][2] = __expf(sacc[nt][2] - nm1);
            sacc[nt][3] = __expf(sacc[nt][3] - nm1);
            rs0 += sacc[nt][0] + sacc[nt][1];
            rs1 += sacc[nt][2] + sacc[nt][3];
        }
        rs0 += __shfl_xor_sync(0xffffffffu, rs0, 1);
        rs0 += __shfl_xor_sync(0xffffffffu, rs0, 2);
        rs1 += __shfl_xor_sync(0xffffffffu, rs1, 1);
        rs1 += __shfl_xor_sync(0xffffffffu, rs1, 2);

        l0 = l0 * sc0 + rs0;  l1 = l1 * sc1 + rs1;
        m0 = nm0;             m1 = nm1;
#pragma unroll
        for (int nt = 0; nt < 8; nt++) {
            o[nt][0] *= sc0; o[nt][1] *= sc0;
            o[nt][2] *= sc1; o[nt][3] *= sc1;
        }

        // O += P V.  P A-fragments built from C-fragments with quad shuffles:
        // col c=kb+lk lives in lane (lm<<2)|(c>>1), element c&1.
        int srcA = (lane & 0x1c) | (lk >> 1);
        int srcB = srcA | 2;
        bool e = (lk & 1);
#pragma unroll
        for (int k8 = 0; k8 < 8; k8++) {
            float p00 = __shfl_sync(0xffffffffu, sacc[k8][0], srcA);
            float p01 = __shfl_sync(0xffffffffu, sacc[k8][1], srcA);
            float p10 = __shfl_sync(0xffffffffu, sacc[k8][2], srcA);
            float p11 = __shfl_sync(0xffffffffu, sacc[k8][3], srcA);
            float q00 = __shfl_sync(0xffffffffu, sacc[k8][0], srcB);
            float q01 = __shfl_sync(0xffffffffu, sacc[k8][1], srcB);
            float q10 = __shfl_sync(0xffffffffu, sacc[k8][2], srcB);
            float q11 = __shfl_sync(0xffffffffu, sacc[k8][3], srcB);
            uint32_t a[4];
            a[0] = f2tf(e ? p01 : p00);
            a[1] = f2tf(e ? p11 : p10);
            a[2] = f2tf(e ? q01 : q00);
            a[3] = f2tf(e ? q11 : q10);
            int kb = k8 * 8;
#pragma unroll
            for (int nt = 0; nt < 8; nt++) {
                uint32_t bb[2];
                bb[0] = f2tf(Vb[(size_t)(kb + lk    ) * VST + nt * 8 + lm]);
                bb[1] = f2tf(Vb[(size_t)(kb + lk + 4) * VST + nt * 8 + lm]);
                mma_tf32(o[nt], a, bb);
            }
        }
    }

    // Epilogue: normalize, write ctx[B,S,D] at head h's columns
    float inv0 = 1.f / l0, inv1 = 1.f / l1;
    int b = bh / H_, h = bh - b * H_;
    int srow = qb + w * 16 + lm;
#pragma unroll
    for (int nt = 0; nt < 8; nt++) {
        int col = h * HD_ + nt * 8 + 2 * lk;
        float2* p0 = (float2*)&g_ctx[((size_t)b * S_ + srow    ) * D_ + col];
        float2* p1 = (float2*)&g_ctx[((size_t)b * S_ + srow + 8) * D_ + col];
        *p0 = make_float2(o[nt][0] * inv0, o[nt][1] * inv0);
        *p1 = make_float2(o[nt][2] * inv1, o[nt][3] * inv1);
    }
}

// ---------------------------------------------------------------------------
// Launch
// ---------------------------------------------------------------------------
extern "C" void kernel_launch(void* const* d_in, const int* in_sizes, int n_in,
                              void* d_out, int out_size) {
    (void)in_sizes; (void)n_in; (void)out_size;
    const float* x  = (const float*)d_in[0];
    const float* Wq = (const float*)d_in[1];
    const float* bq = (const float*)d_in[2];
    const float* Wk = (const float*)d_in[3];
    const float* bk = (const float*)d_in[4];
    const float* Wv = (const float*)d_in[5];
    const float* bv = (const float*)d_in[6];
    const float* Wo = (const float*)d_in[7];
    const float* bo = (const float*)d_in[8];
    float* out = (float*)d_out;

    float *xt, *q, *k, *v, *ctx;
    cudaGetSymbolAddress((void**)&xt,  g_xt);
    cudaGetSymbolAddress((void**)&q,   g_q);
    cudaGetSymbolAddress((void**)&k,   g_k);
    cudaGetSymbolAddress((void**)&v,   g_v);
    cudaGetSymbolAddress((void**)&ctx, g_ctx);

    cudaFuncSetAttribute(gemm_tf32<1>, cudaFuncAttributeMaxDynamicSharedMemorySize,
                         GEMM_SMEM_BYTES);
    cudaFuncSetAttribute(gemm_tf32<2>, cudaFuncAttributeMaxDynamicSharedMemorySize,
                         GEMM_SMEM_BYTES);
    cudaFuncSetAttribute(flash_attn, cudaFuncAttributeMaxDynamicSharedMemorySize,
                         ATTN_SMEM_BYTES);

    // 1) PE table
    pe_kernel<<<(D_ * S_ + 255) / 256, 256>>>();
    // 2) x + PE, transpose to [B,S,D]
    addpe_transpose<<<dim3(S_ / 32, D_ / 32, B_), dim3(32, 8)>>>(x);
    // 3) Q/K/V projections -> [B,H,S,hd]
    dim3 ggrid(D_ / 128, BS_ / 128);
    gemm_tf32<1><<<ggrid, 256, GEMM_SMEM_BYTES>>>(xt, Wq, bq, q, BS_, D_, D_);
    gemm_tf32<1><<<ggrid, 256, GEMM_SMEM_BYTES>>>(xt, Wk, bk, k, BS_, D_, D_);
    gemm_tf32<1><<<ggrid, 256, GEMM_SMEM_BYTES>>>(xt, Wv, bv, v, BS_, D_, D_);
    // 4) attention -> ctx[B,S,D]
    flash_attn<<<dim3(S_ / 128, B_ * H_), 256, ATTN_SMEM_BYTES>>>();
    // 5) output projection, transposed epilogue -> [B,D,S]
    gemm_tf32<2><<<ggrid, 256, GEMM_SMEM_BYTES>>>(ctx, Wo, bo, out, BS_, D_, D_);
}

// round 4
// speedup vs baseline: 1.8727x; 1.1095x over previous
#include <cuda_runtime.h>
#include <cstdint>
#include <math.h>

// Problem constants
#define B_  4
#define D_  1024
#define S_  2048
#define H_  16
#define HD_ 64
#define BS_ (B_*S_)

// ---------------------------------------------------------------------------
// Scratch (static device globals — no allocation allowed)
// ---------------------------------------------------------------------------
__device__ float g_pe  [D_*S_];            //  8 MB  positional encoding [D][S]
__device__ float g_xt  [BS_*(size_t)D_];   // 33.5 MB  x transposed+PE (tf32)
__device__ float g_q   [BS_*(size_t)D_];   // Q [B,H,S,hd] (tf32-rounded)
__device__ float g_k   [BS_*(size_t)D_];   // K [B,H,S,hd] (tf32-rounded)
__device__ float g_v   [BS_*(size_t)D_];   // V [B,H,S,hd] (tf32-rounded)
__device__ float g_ctx [BS_*(size_t)D_];   // attention out [B,S,D] (tf32)
__device__ float g_wqkv[3*D_*(size_t)D_];  // stacked rounded Wq|Wk|Wv [3072,1024]
__device__ float g_wo  [D_*(size_t)D_];    // rounded Wo

// ---------------------------------------------------------------------------
// Helpers
// ---------------------------------------------------------------------------
__device__ __forceinline__ uint32_t f2tf(float x) {
    uint32_t r;
    asm("cvt.rna.tf32.f32 %0, %1;" : "=r"(r) : "f"(x));
    return r;
}
__device__ __forceinline__ float tf32r(float x) {   // round-to-nearest tf32, as float
    return __uint_as_float(f2tf(x));
}

__device__ __forceinline__ void mma_tf32(float* c, const uint32_t* a, const uint32_t* b) {
    asm volatile(
        "mma.sync.aligned.m16n8k8.row.col.f32.tf32.tf32.f32 "
        "{%0,%1,%2,%3}, {%4,%5,%6,%7}, {%8,%9}, {%0,%1,%2,%3};\n"
        : "+f"(c[0]), "+f"(c[1]), "+f"(c[2]), "+f"(c[3])
        : "r"(a[0]), "r"(a[1]), "r"(a[2]), "r"(a[3]), "r"(b[0]), "r"(b[1]));
}

__device__ __forceinline__ uint32_t s2u(const void* p) {
    return (uint32_t)__cvta_generic_to_shared(p);
}
__device__ __forceinline__ void cpasync16(uint32_t dst, const void* src) {
    asm volatile("cp.async.ca.shared.global [%0], [%1], 16;\n" :: "r"(dst), "l"(src));
}
__device__ __forceinline__ void cp_commit() {
    asm volatile("cp.async.commit_group;\n");
}
__device__ __forceinline__ void cp_wait0() {
    asm volatile("cp.async.wait_group 0;\n");
}

// ---------------------------------------------------------------------------
// 0) Weight prep: round Wq|Wk|Wv (stacked) and Wo to tf32 in scratch.
// ---------------------------------------------------------------------------
__global__ void weight_prep(const float* __restrict__ Wq, const float* __restrict__ Wk,
                            const float* __restrict__ Wv, const float* __restrict__ Wo) {
    int idx4 = blockIdx.x * blockDim.x + threadIdx.x;     // one float4 each
    const int NW = D_ * D_ / 4;                           // 262144 float4 per matrix
    if (idx4 < NW) {
        float4 a = ((const float4*)Wq)[idx4];
        float4 b = ((const float4*)Wk)[idx4];
        float4 c = ((const float4*)Wv)[idx4];
        float4 d = ((const float4*)Wo)[idx4];
        ((float4*)g_wqkv)[idx4] =
            make_float4(tf32r(a.x), tf32r(a.y), tf32r(a.z), tf32r(a.w));
        ((float4*)g_wqkv)[idx4 + NW] =
            make_float4(tf32r(b.x), tf32r(b.y), tf32r(b.z), tf32r(b.w));
        ((float4*)g_wqkv)[idx4 + 2 * NW] =
            make_float4(tf32r(c.x), tf32r(c.y), tf32r(c.z), tf32r(c.w));
        ((float4*)g_wo)[idx4] =
            make_float4(tf32r(d.x), tf32r(d.y), tf32r(d.z), tf32r(d.w));
    }
}

// ---------------------------------------------------------------------------
// 1) Positional encoding table  pe[d][s]  (double trig for exact fp32 match)
// ---------------------------------------------------------------------------
__global__ void pe_kernel() {
    int idx = blockIdx.x * blockDim.x + threadIdx.x;
    if (idx >= D_ * S_) return;
    int d = idx / S_;
    int s = idx - d * S_;
    double freq_d = exp((double)(d & ~1) * (-9.210340371976184 / (double)D_));
    float  freq   = (float)freq_d;
    float  ang    = (float)s * freq;
    float  val    = (d & 1) ? (float)cos((double)ang) : (float)sin((double)ang);
    g_pe[idx] = val;
}

// ---------------------------------------------------------------------------
// 2) x[B,D,S] + pe[D,S]  ->  xt[B,S,D], tf32-rounded at store
// ---------------------------------------------------------------------------
__global__ void addpe_transpose(const float* __restrict__ x) {
    __shared__ float tile[32][33];
    int b  = blockIdx.z;
    int d0 = blockIdx.y * 32;
    int s0 = blockIdx.x * 32;
    int tx = threadIdx.x, ty = threadIdx.y;  // (32, 8)
#pragma unroll
    for (int j = 0; j < 4; j++) {
        int d = d0 + ty + j * 8;
        tile[ty + j * 8][tx] = x[((size_t)b * D_ + d) * S_ + s0 + tx]
                             + g_pe[(size_t)d * S_ + s0 + tx];
    }
    __syncthreads();
#pragma unroll
    for (int j = 0; j < 4; j++) {
        int s = s0 + ty + j * 8;
        g_xt[((size_t)b * S_ + s) * D_ + d0 + tx] = tf32r(tile[tx][ty + j * 8]);
    }
}

// ---------------------------------------------------------------------------
// 3/5) TF32 GEMM, cp.async double-buffered; inputs pre-rounded to tf32 so
//      mma operands are raw smem loads (no cvt in the inner loop).
//      BM=BN=128, BK=32, 256 thr, 8 warps.  Smem [row][k], stride 36.
// MODE 1: fused QKV, N=3072, scatter to q/k/v [B,H,S,hd], tf32-rounded.
// MODE 2: O-proj, transpose epilogue to [B,D,S], full fp32.
// ---------------------------------------------------------------------------
#define GST 36
#define GEMM_SMEM_BYTES (2 * 2 * 128 * GST * 4)   // 73728

template <int MODE>
__global__ void __launch_bounds__(256, 2)
gemm_tf32(const float* __restrict__ A, const float* __restrict__ W,
          const float* __restrict__ b0p, const float* __restrict__ b1p,
          const float* __restrict__ b2p,
          float* __restrict__ C0, float* __restrict__ C1, float* __restrict__ C2,
          int K) {
    extern __shared__ float sm[];
    float* As = sm;                    // [2][128][36]
    float* Bs = sm + 2 * 128 * GST;    // [2][128][36]
    uint32_t sA = s2u(As), sB = s2u(Bs);

    int t    = threadIdx.x;
    int wid  = t >> 5, lane = t & 31;
    int lm   = lane >> 2, lk = lane & 3;
    int wm   = (wid >> 1) * 32;
    int wn   = (wid & 1) * 64;
    int bm   = blockIdx.y * 128;
    int bn   = blockIdx.x * 128;

    float c[2][8][4];
#pragma unroll
    for (int mt = 0; mt < 2; mt++)
#pragma unroll
        for (int nt = 0; nt < 8; nt++)
#pragma unroll
            for (int i = 0; i < 4; i++) c[mt][nt][i] = 0.f;

    int rowg = t >> 3;        // 0..31
    int chk  = t & 7;         // 0..7

    auto issue = [&](int k0, int p) {
#pragma unroll
        for (int i = 0; i < 4; i++) {
            int r = rowg + i * 32;
            cpasync16(sA + (((p * 128 + r) * GST) + chk * 4) * 4,
                      A + (size_t)(bm + r) * K + k0 + chk * 4);
            cpasync16(sB + (((p * 128 + r) * GST) + chk * 4) * 4,
                      W + (size_t)(bn + r) * K + k0 + chk * 4);
        }
        cp_commit();
    };

    int ntiles = K >> 5;
    issue(0, 0);

    for (int it = 0; it < ntiles; it++) {
        int p = it & 1;
        cp_wait0();
        __syncthreads();
        if (it + 1 < ntiles) issue((it + 1) << 5, 1 - p);

        const float* Ab = As + p * 128 * GST;
        const float* Bb = Bs + p * 128 * GST;
#pragma unroll
        for (int k8 = 0; k8 < 4; k8++) {
            int kb = k8 * 8;
            uint32_t a[2][4];
#pragma unroll
            for (int mt = 0; mt < 2; mt++) {
                int r = wm + mt * 16 + lm;
                a[mt][0] = __float_as_uint(Ab[(size_t)(r    ) * GST + kb + lk    ]);
                a[mt][1] = __float_as_uint(Ab[(size_t)(r + 8) * GST + kb + lk    ]);
                a[mt][2] = __float_as_uint(Ab[(size_t)(r    ) * GST + kb + lk + 4]);
                a[mt][3] = __float_as_uint(Ab[(size_t)(r + 8) * GST + kb + lk + 4]);
            }
            uint32_t bf[8][2];
#pragma unroll
            for (int nt = 0; nt < 8; nt++) {
                int cn = wn + nt * 8 + lm;
                bf[nt][0] = __float_as_uint(Bb[(size_t)cn * GST + kb + lk    ]);
                bf[nt][1] = __float_as_uint(Bb[(size_t)cn * GST + kb + lk + 4]);
            }
#pragma unroll
            for (int mt = 0; mt < 2; mt++)
#pragma unroll
                for (int nt = 0; nt < 8; nt++)
                    mma_tf32(c[mt][nt], a[mt], bf[nt]);
        }
        __syncthreads();
    }

    // Epilogue
#pragma unroll
    for (int mt = 0; mt < 2; mt++) {
        int r0 = bm + wm + mt * 16 + lm;
#pragma unroll
        for (int nt = 0; nt < 8; nt++) {
            int col = bn + wn + nt * 8 + 2 * lk;     // 0..3071 (MODE1) / 0..1023
            if (MODE == 1) {
                int which = col >> 10;
                int cc    = col & 1023;
                const float* bias = (which == 0) ? b0p : (which == 1) ? b1p : b2p;
                float* C          = (which == 0) ? C0  : (which == 1) ? C1  : C2;
                float bv0 = bias[cc], bv1 = bias[cc + 1];
                float v00 = tf32r(c[mt][nt][0] + bv0), v01 = tf32r(c[mt][nt][1] + bv1);
                float v10 = tf32r(c[mt][nt][2] + bv0), v11 = tf32r(c[mt][nt][3] + bv1);
                int b  = r0 / S_;
                int h  = cc >> 6;
                int hd = cc & 63;
                int s  = r0 - b * S_;
                float2* p0 = (float2*)&C[(((size_t)(b * H_ + h)) * S_ + s    ) * HD_ + hd];
                float2* p1 = (float2*)&C[(((size_t)(b * H_ + h)) * S_ + s + 8) * HD_ + hd];
                *p0 = make_float2(v00, v01);
                *p1 = make_float2(v10, v11);
            } else {
                float bv0 = b0p[col], bv1 = b0p[col + 1];
                float v00 = c[mt][nt][0] + bv0, v01 = c[mt][nt][1] + bv1;
                float v10 = c[mt][nt][2] + bv0, v11 = c[mt][nt][3] + bv1;
                int b = r0 / S_;
                int s = r0 - b * S_;
                C0[((size_t)b * D_ + col    ) * S_ + s    ] = v00;
                C0[((size_t)b * D_ + col + 1) * S_ + s    ] = v01;
                C0[((size_t)b * D_ + col    ) * S_ + s + 8] = v10;
                C0[((size_t)b * D_ + col + 1) * S_ + s + 8] = v11;
            }
        }
    }
}

// ---------------------------------------------------------------------------
// 4) Flash attention.  Grid (S/128, B*H), 256 threads (8 warps x 16 q-rows).
//    Q/K/V pre-rounded tf32 -> no cvt except P fragments.
// ---------------------------------------------------------------------------
#define QST 132   // 132%32==4
#define KST 68    //  68%32==4
#define VST 72    //  72%32==8
#define ATTN_SMEM_BYTES ((64*QST + 2*64*KST + 2*64*VST) * 4)   // 105472

__global__ void __launch_bounds__(256, 2)
flash_attn() {
    extern __shared__ float sm[];
    float* Qs = sm;                        // [64 d][132] (scaled, tf32-exact)
    float* Ks = sm + 64 * QST;             // [2][64 key][68]
    float* Vs = Ks + 2 * 64 * KST;         // [2][64 key][72]
    uint32_t sK = s2u(Ks), sV = s2u(Vs);

    int t = threadIdx.x, w = t >> 5, lane = t & 31;
    int lm = lane >> 2, lk = lane & 3;
    int bh = blockIdx.y;
    int qb = blockIdx.x * 128;
    size_t base = (size_t)bh * S_ * HD_;

    int rowg = t >> 4;   // 0..15
    int chk  = t & 15;   // 0..15

    auto issue = [&](int kt, int p) {
#pragma unroll
        for (int i = 0; i < 4; i++) {
            int r = rowg + i * 16;
            cpasync16(sK + (((p * 64 + r) * KST) + chk * 4) * 4,
                      g_k + base + (size_t)(kt + r) * HD_ + chk * 4);
            cpasync16(sV + (((p * 64 + r) * VST) + chk * 4) * 4,
                      g_v + base + (size_t)(kt + r) * HD_ + chk * 4);
        }
        cp_commit();
    };

    // Q tile: scale by 0.125 (exact power of two -> stays tf32), store [d][row]
#pragma unroll
    for (int i = 0; i < 8; i++) {
        int r = rowg + i * 16;
        float4 v = *(const float4*)(g_q + base + (size_t)(qb + r) * HD_ + chk * 4);
        Qs[(chk * 4 + 0) * QST + r] = v.x * 0.125f;
        Qs[(chk * 4 + 1) * QST + r] = v.y * 0.125f;
        Qs[(chk * 4 + 2) * QST + r] = v.z * 0.125f;
        Qs[(chk * 4 + 3) * QST + r] = v.w * 0.125f;
    }

    issue(0, 0);

    float o[8][4];
#pragma unroll
    for (int nt = 0; nt < 8; nt++)
#pragma unroll
        for (int i = 0; i < 4; i++) o[nt][i] = 0.f;
    float m0 = -INFINITY, m1 = -INFINITY, l0 = 0.f, l1 = 0.f;

    const int NT = S_ / 64;
    for (int it = 0; it < NT; it++) {
        int p = it & 1;
        cp_wait0();
        __syncthreads();
        if (it + 1 < NT) issue((it + 1) * 64, 1 - p);

        const float* Kb = Ks + p * 64 * KST;
        const float* Vb = Vs + p * 64 * VST;

        // S = Q K^T
        float sacc[8][4];
#pragma unroll
        for (int nt = 0; nt < 8; nt++)
#pragma unroll
            for (int i = 0; i < 4; i++) sacc[nt][i] = 0.f;

        int r = w * 16 + lm;
#pragma unroll
        for (int k8 = 0; k8 < 8; k8++) {
            int kb = k8 * 8;
            uint32_t a[4];
            a[0] = __float_as_uint(Qs[(kb + lk    ) * QST + r    ]);
            a[1] = __float_as_uint(Qs[(kb + lk    ) * QST + r + 8]);
            a[2] = __float_as_uint(Qs[(kb + lk + 4) * QST + r    ]);
            a[3] = __float_as_uint(Qs[(kb + lk + 4) * QST + r + 8]);
#pragma unroll
            for (int nt = 0; nt < 8; nt++) {
                uint32_t bb[2];
                bb[0] = __float_as_uint(Kb[(size_t)(nt * 8 + lm) * KST + kb + lk    ]);
                bb[1] = __float_as_uint(Kb[(size_t)(nt * 8 + lm) * KST + kb + lk + 4]);
                mma_tf32(sacc[nt], a, bb);
            }
        }

        // Online softmax (rows lm, lm+8)
        float mx0 = -INFINITY, mx1 = -INFINITY;
#pragma unroll
        for (int nt = 0; nt < 8; nt++) {
            mx0 = fmaxf(mx0, fmaxf(sacc[nt][0], sacc[nt][1]));
            mx1 = fmaxf(mx1, fmaxf(sacc[nt][2], sacc[nt][3]));
        }
        mx0 = fmaxf(mx0, __shfl_xor_sync(0xffffffffu, mx0, 1));
        mx0 = fmaxf(mx0, __shfl_xor_sync(0xffffffffu, mx0, 2));
        mx1 = fmaxf(mx1, __shfl_xor_sync(0xffffffffu, mx1, 1));
        mx1 = fmaxf(mx1, __shfl_xor_sync(0xffffffffu, mx1, 2));

        float nm0 = fmaxf(m0, mx0), nm1 = fmaxf(m1, mx1);
        float sc0 = __expf(m0 - nm0), sc1 = __expf(m1 - nm1);
        float rs0 = 0.f, rs1 = 0.f;
#pragma unroll
        for (int nt = 0; nt < 8; nt++) {
            sacc[nt][0] = __expf(sacc[nt][0] - nm0);
            sacc[nt][1] = __expf(sacc[nt][1] - nm0);
            sacc[nt][2] = __expf(sacc[nt][2] - nm1);
            sacc[nt][3] = __expf(sacc[nt][3] - nm1);
            rs0 += sacc[nt][0] + sacc[nt][1];
            rs1 += sacc[nt][2] + sacc[nt][3];
        }
        rs0 += __shfl_xor_sync(0xffffffffu, rs0, 1);
        rs0 += __shfl_xor_sync(0xffffffffu, rs0, 2);
        rs1 += __shfl_xor_sync(0xffffffffu, rs1, 1);
        rs1 += __shfl_xor_sync(0xffffffffu, rs1, 2);

        l0 = l0 * sc0 + rs0;  l1 = l1 * sc1 + rs1;
        m0 = nm0;             m1 = nm1;
#pragma unroll
        for (int nt = 0; nt < 8; nt++) {
            o[nt][0] *= sc0; o[nt][1] *= sc0;
            o[nt][2] *= sc1; o[nt][3] *= sc1;
        }

        // O += P V  (P A-frags from C-frags via quad shuffles)
        int srcA = (lane & 0x1c) | (lk >> 1);
        int srcB = srcA | 2;
        bool e = (lk & 1);
#pragma unroll
        for (int k8 = 0; k8 < 8; k8++) {
            float p00 = __shfl_sync(0xffffffffu, sacc[k8][0], srcA);
            float p01 = __shfl_sync(0xffffffffu, sacc[k8][1], srcA);
            float p10 = __shfl_sync(0xffffffffu, sacc[k8][2], srcA);
            float p11 = __shfl_sync(0xffffffffu, sacc[k8][3], srcA);
            float q00 = __shfl_sync(0xffffffffu, sacc[k8][0], srcB);
            float q01 = __shfl_sync(0xffffffffu, sacc[k8][1], srcB);
            float q10 = __shfl_sync(0xffffffffu, sacc[k8][2], srcB);
            float q11 = __shfl_sync(0xffffffffu, sacc[k8][3], srcB);
            uint32_t a[4];
            a[0] = f2tf(e ? p01 : p00);
            a[1] = f2tf(e ? p11 : p10);
            a[2] = f2tf(e ? q01 : q00);
            a[3] = f2tf(e ? q11 : q10);
            int kb = k8 * 8;
#pragma unroll
            for (int nt = 0; nt < 8; nt++) {
                uint32_t bb[2];
                bb[0] = __float_as_uint(Vb[(size_t)(kb + lk    ) * VST + nt * 8 + lm]);
                bb[1] = __float_as_uint(Vb[(size_t)(kb + lk + 4) * VST + nt * 8 + lm]);
                mma_tf32(o[nt], a, bb);
            }
        }
    }

    // Epilogue: normalize, tf32-round (ctx feeds the O-proj GEMM)
    float inv0 = 1.f / l0, inv1 = 1.f / l1;
    int b = bh / H_, h = bh - b * H_;
    int srow = qb + w * 16 + lm;
#pragma unroll
    for (int nt = 0; nt < 8; nt++) {
        int col = h * HD_ + nt * 8 + 2 * lk;
        float2* p0 = (float2*)&g_ctx[((size_t)b * S_ + srow    ) * D_ + col];
        float2* p1 = (float2*)&g_ctx[((size_t)b * S_ + srow + 8) * D_ + col];
        *p0 = make_float2(tf32r(o[nt][0] * inv0), tf32r(o[nt][1] * inv0));
        *p1 = make_float2(tf32r(o[nt][2] * inv1), tf32r(o[nt][3] * inv1));
    }
}

// ---------------------------------------------------------------------------
// Launch
// ---------------------------------------------------------------------------
extern "C" void kernel_launch(void* const* d_in, const int* in_sizes, int n_in,
                              void* d_out, int out_size) {
    (void)in_sizes; (void)n_in; (void)out_size;
    const float* x  = (const float*)d_in[0];
    const float* Wq = (const float*)d_in[1];
    const float* bq = (const float*)d_in[2];
    const float* Wk = (const float*)d_in[3];
    const float* bk = (const float*)d_in[4];
    const float* Wv = (const float*)d_in[5];
    const float* bv = (const float*)d_in[6];
    const float* Wo = (const float*)d_in[7];
    const float* bo = (const float*)d_in[8];
    float* out = (float*)d_out;

    float *xt, *q, *k, *v, *ctx, *wqkv, *wo;
    cudaGetSymbolAddress((void**)&xt,   g_xt);
    cudaGetSymbolAddress((void**)&q,    g_q);
    cudaGetSymbolAddress((void**)&k,    g_k);
    cudaGetSymbolAddress((void**)&v,    g_v);
    cudaGetSymbolAddress((void**)&ctx,  g_ctx);
    cudaGetSymbolAddress((void**)&wqkv, g_wqkv);
    cudaGetSymbolAddress((void**)&wo,   g_wo);

    cudaFuncSetAttribute(gemm_tf32<1>, cudaFuncAttributeMaxDynamicSharedMemorySize,
                         GEMM_SMEM_BYTES);
    cudaFuncSetAttribute(gemm_tf32<2>, cudaFuncAttributeMaxDynamicSharedMemorySize,
                         GEMM_SMEM_BYTES);
    cudaFuncSetAttribute(flash_attn, cudaFuncAttributeMaxDynamicSharedMemorySize,
                         ATTN_SMEM_BYTES);

    // 0) weights -> tf32 scratch
    weight_prep<<<(D_ * D_ / 4 + 255) / 256, 256>>>(Wq, Wk, Wv, Wo);
    // 1) PE table
    pe_kernel<<<(D_ * S_ + 255) / 256, 256>>>();
    // 2) x + PE -> xt[B,S,D] (tf32)
    addpe_transpose<<<dim3(S_ / 32, D_ / 32, B_), dim3(32, 8)>>>(x);
    // 3) fused QKV projection (N=3072) -> q/k/v [B,H,S,hd]
    gemm_tf32<1><<<dim3(3 * D_ / 128, BS_ / 128), 256, GEMM_SMEM_BYTES>>>(
        xt, wqkv, bq, bk, bv, q, k, v, D_);
    // 4) attention -> ctx[B,S,D] (tf32)
    flash_attn<<<dim3(S_ / 128, B_ * H_), 256, ATTN_SMEM_BYTES>>>();
    // 5) output projection -> [B,D,S] fp32
    gemm_tf32<2><<<dim3(D_ / 128, BS_ / 128), 256, GEMM_SMEM_BYTES>>>(
        ctx, wo, bo, nullptr, nullptr, out, nullptr, nullptr, D_);
}

// round 9
// speedup vs baseline: 2.6797x; 1.4309x over previous
#include <cuda_runtime.h>
#include <cuda_fp16.h>
#include <cstdint>
#include <math.h>

// Problem constants
#define B_  4
#define D_  1024
#define S_  2048
#define H_  16
#define HD_ 64
#define BS_ (B_*S_)

// ---------------------------------------------------------------------------
// Scratch (static device globals — no allocation allowed)
// ---------------------------------------------------------------------------
__device__ float  g_pe  [D_*S_];             // positional encoding [D][S]
__device__ __half g_xt  [BS_*(size_t)D_];    // x+PE, [B,S,D]  fp16
__device__ __half g_q   [BS_*(size_t)D_];    // Q/8  [BH][S][hd] fp16
__device__ __half g_k   [BS_*(size_t)D_];    // K    [BH][S][hd] fp16
__device__ __half g_v   [BS_*(size_t)D_];    // V    [BH][S][hd] fp16 (same as K)
__device__ __half g_ctx [BS_*(size_t)D_];    // attention out [B,S,D] fp16
__device__ __half g_wqkv[3*D_*(size_t)D_];   // Wq|Wk|Wv stacked [3072][1024] fp16
__device__ __half g_wo  [D_*(size_t)D_];     // Wo fp16

// ---------------------------------------------------------------------------
// Helpers
// ---------------------------------------------------------------------------
__device__ __forceinline__ uint32_t s2u(const void* p) {
    return (uint32_t)__cvta_generic_to_shared(p);
}
__device__ __forceinline__ void cpasync16(uint32_t dst, const void* src) {
    asm volatile("cp.async.ca.shared.global [%0], [%1], 16;\n" :: "r"(dst), "l"(src));
}
__device__ __forceinline__ void cp_commit() {
    asm volatile("cp.async.commit_group;\n");
}
__device__ __forceinline__ void cp_wait0() {
    asm volatile("cp.async.wait_group 0;\n");
}

// fp16 mma: m16n8k16, fp32 accumulate
__device__ __forceinline__ void mma_f16(float* c, const uint32_t* a, const uint32_t* b) {
    asm volatile(
        "mma.sync.aligned.m16n8k16.row.col.f32.f16.f16.f32 "
        "{%0,%1,%2,%3}, {%4,%5,%6,%7}, {%8,%9}, {%0,%1,%2,%3};\n"
        : "+f"(c[0]), "+f"(c[1]), "+f"(c[2]), "+f"(c[3])
        : "r"(a[0]), "r"(a[1]), "r"(a[2]), "r"(a[3]), "r"(b[0]), "r"(b[1]));
}

// ---------------------------------------------------------------------------
// 0) Weight prep: convert weights to fp16 (Wq|Wk|Wv stacked, Wo)
// ---------------------------------------------------------------------------
__global__ void weight_prep(const float* __restrict__ Wq, const float* __restrict__ Wk,
                            const float* __restrict__ Wv, const float* __restrict__ Wo) {
    int idx4 = blockIdx.x * blockDim.x + threadIdx.x;
    const int NW = D_ * D_ / 4;
    if (idx4 >= NW) return;
    float4 a = ((const float4*)Wq)[idx4];
    float4 b = ((const float4*)Wk)[idx4];
    float4 c = ((const float4*)Wv)[idx4];
    float4 d = ((const float4*)Wo)[idx4];
    __half2* wq2 = (__half2*)g_wqkv;
    __half2* wo2 = (__half2*)g_wo;
    wq2[2*idx4    ]        = __floats2half2_rn(a.x, a.y);
    wq2[2*idx4 + 1]        = __floats2half2_rn(a.z, a.w);
    wq2[2*(idx4+NW)    ]   = __floats2half2_rn(b.x, b.y);
    wq2[2*(idx4+NW) + 1]   = __floats2half2_rn(b.z, b.w);
    wq2[2*(idx4+2*NW)    ] = __floats2half2_rn(c.x, c.y);
    wq2[2*(idx4+2*NW) + 1] = __floats2half2_rn(c.z, c.w);
    wo2[2*idx4    ]        = __floats2half2_rn(d.x, d.y);
    wo2[2*idx4 + 1]        = __floats2half2_rn(d.z, d.w);
}

// ---------------------------------------------------------------------------
// 1) Positional encoding table (double trig for exact fp32 match)
// ---------------------------------------------------------------------------
__global__ void pe_kernel() {
    int idx = blockIdx.x * blockDim.x + threadIdx.x;
    if (idx >= D_ * S_) return;
    int d = idx / S_;
    int s = idx - d * S_;
    double freq_d = exp((double)(d & ~1) * (-9.210340371976184 / (double)D_));
    float  freq   = (float)freq_d;
    float  ang    = (float)s * freq;
    float  val    = (d & 1) ? (float)cos((double)ang) : (float)sin((double)ang);
    g_pe[idx] = val;
}

// ---------------------------------------------------------------------------
// 2) x[B,D,S] + pe[D,S]  ->  xt[B,S,D]  fp16
// ---------------------------------------------------------------------------
__global__ void addpe_transpose(const float* __restrict__ x) {
    __shared__ float tile[32][33];
    int b  = blockIdx.z;
    int d0 = blockIdx.y * 32;
    int s0 = blockIdx.x * 32;
    int tx = threadIdx.x, ty = threadIdx.y;  // (32, 8)
#pragma unroll
    for (int j = 0; j < 4; j++) {
        int d = d0 + ty + j * 8;
        tile[ty + j * 8][tx] = x[((size_t)b * D_ + d) * S_ + s0 + tx]
                             + g_pe[(size_t)d * S_ + s0 + tx];
    }
    __syncthreads();
#pragma unroll
    for (int j = 0; j < 4; j++) {
        int s = s0 + ty + j * 8;
        g_xt[((size_t)b * S_ + s) * D_ + d0 + tx] =
            __float2half_rn(tile[tx][ty + j * 8]);
    }
}

// ---------------------------------------------------------------------------
// 3/5) fp16 GEMM:  C[M,N] = A[M,K] @ W[N,K]^T + bias.
//      BM=BN=128, BK=32, 256 thr (8 warps 4x2), warp tile 32x64,
//      mma m16n8k16 fp32-acc.  Smem [row][k] half, stride 40.
// MODE 1: fused QKV (N=3072): Q scaled 1/8; Q/K/V all -> [BH][S][hd] fp16.
// MODE 2: O-proj: A=ctx fp16, output fp32 transposed to [B,D,S].
// ---------------------------------------------------------------------------
#define GST 40   // halves per smem row

template <int MODE>
__global__ void __launch_bounds__(256, 2)
gemm_f16(const __half* __restrict__ A, const __half* __restrict__ W,
         const float* __restrict__ b0p, const float* __restrict__ b1p,
         const float* __restrict__ b2p,
         void* __restrict__ C0v, void* __restrict__ C1v, void* __restrict__ C2v,
         int K) {
    __shared__ __half As[2][128][GST];
    __shared__ __half Bs[2][128][GST];

    int t    = threadIdx.x;
    int wid  = t >> 5, lane = t & 31;
    int lm   = lane >> 2, lk = lane & 3;
    int wm   = (wid >> 1) * 32;
    int wn   = (wid & 1) * 64;
    int bm   = blockIdx.y * 128;
    int bn   = blockIdx.x * 128;

    float c[2][8][4];
#pragma unroll
    for (int mt = 0; mt < 2; mt++)
#pragma unroll
        for (int nt = 0; nt < 8; nt++)
#pragma unroll
            for (int i = 0; i < 4; i++) c[mt][nt][i] = 0.f;

    int rowg = t >> 2;        // 0..63
    int chk  = t & 3;         // 0..3  (4 x 16B chunks per 32-half row)

    auto issue = [&](int k0, int p) {
#pragma unroll
        for (int i = 0; i < 2; i++) {
            int r = rowg + i * 64;
            cpasync16(s2u(&As[p][r][chk * 8]),
                      A + (size_t)(bm + r) * K + k0 + chk * 8);
            cpasync16(s2u(&Bs[p][r][chk * 8]),
                      W + (size_t)(bn + r) * K + k0 + chk * 8);
        }
        cp_commit();
    };

    int NT = K >> 5;
    issue(0, 0);

    for (int it = 0; it < NT; it++) {
        int p = it & 1;
        cp_wait0();
        __syncthreads();
        if (it + 1 < NT) issue((it + 1) << 5, 1 - p);

        const __half* Ab = &As[p][0][0];
        const __half* Bb = &Bs[p][0][0];
#pragma unroll
        for (int ks = 0; ks < 2; ks++) {
            int kb = ks * 16;
            uint32_t a[2][4];
#pragma unroll
            for (int mt = 0; mt < 2; mt++) {
                int r = wm + mt * 16 + lm;
                a[mt][0] = *(const uint32_t*)&Ab[(r    ) * GST + kb + 2 * lk    ];
                a[mt][1] = *(const uint32_t*)&Ab[(r + 8) * GST + kb + 2 * lk    ];
                a[mt][2] = *(const uint32_t*)&Ab[(r    ) * GST + kb + 2 * lk + 8];
                a[mt][3] = *(const uint32_t*)&Ab[(r + 8) * GST + kb + 2 * lk + 8];
            }
            uint32_t bf[8][2];
#pragma unroll
            for (int nt = 0; nt < 8; nt++) {
                int cn = wn + nt * 8 + lm;
                bf[nt][0] = *(const uint32_t*)&Bb[cn * GST + kb + 2 * lk    ];
                bf[nt][1] = *(const uint32_t*)&Bb[cn * GST + kb + 2 * lk + 8];
            }
#pragma unroll
            for (int mt = 0; mt < 2; mt++)
#pragma unroll
                for (int nt = 0; nt < 8; nt++)
                    mma_f16(c[mt][nt], a[mt], bf[nt]);
        }
        __syncthreads();
    }

    // Epilogue
    int which = bn >> 10;       // MODE 1: 0=Q 1=K 2=V (uniform per CTA)
    int cc0   = bn & 1023;
    float scale = (MODE == 1 && which == 0) ? 0.125f : 1.0f;
#pragma unroll
    for (int mt = 0; mt < 2; mt++) {
        int r0 = bm + wm + mt * 16 + lm;
        int b  = r0 / S_;
        int s  = r0 - b * S_;
#pragma unroll
        for (int nt = 0; nt < 8; nt++) {
            int col = wn + nt * 8 + 2 * lk;
            if (MODE == 1) {
                int cc = cc0 + col;
                const float* bias = (which == 0) ? b0p : (which == 1) ? b1p : b2p;
                __half* C = (which == 0) ? (__half*)C0v
                          : (which == 1) ? (__half*)C1v : (__half*)C2v;
                float bv0 = bias[cc], bv1 = bias[cc + 1];
                float v00 = (c[mt][nt][0] + bv0) * scale;
                float v01 = (c[mt][nt][1] + bv1) * scale;
                float v10 = (c[mt][nt][2] + bv0) * scale;
                float v11 = (c[mt][nt][3] + bv1) * scale;
                int h  = cc >> 6;
                int hd = cc & 63;
                __half2* p0 = (__half2*)&C[(((size_t)(b * H_ + h)) * S_ + s    ) * HD_ + hd];
                __half2* p1 = (__half2*)&C[(((size_t)(b * H_ + h)) * S_ + s + 8) * HD_ + hd];
                *p0 = __floats2half2_rn(v00, v01);
                *p1 = __floats2half2_rn(v10, v11);
            } else {            // O-proj: fp32 transposed [B,D,S]
                int gcol = bn + col;                 // <-- FIX: bn was missing
                float* C = (float*)C0v;
                float bv0 = b0p[gcol], bv1 = b0p[gcol + 1];
                C[((size_t)b * D_ + gcol    ) * S_ + s    ] = c[mt][nt][0] + bv0;
                C[((size_t)b * D_ + gcol + 1) * S_ + s    ] = c[mt][nt][1] + bv1;
                C[((size_t)b * D_ + gcol    ) * S_ + s + 8] = c[mt][nt][2] + bv0;
                C[((size_t)b * D_ + gcol + 1) * S_ + s + 8] = c[mt][nt][3] + bv1;
            }
        }
    }
}

// ---------------------------------------------------------------------------
// 4) Flash attention, fp16 mma.  Grid (S/128, B*H), 256 thr (8 warps x 16 q).
//    Q/K/V smem all [row][d] natural layout (proven R4 scheme).
//    P via per-warp fp16 smem (plain row-major); PV B-fragments from two
//    scalar half loads of V[key][d] + pack.  No transposes, no shuffles.
// ---------------------------------------------------------------------------
#define AST 72   // halves per smem K/V/Q row
#define PST 72   // halves per P row
#define ATTN_SMEM_BYTES ((128*AST + 2*64*AST + 2*64*AST + 8*16*PST) * 2)  // 73728

__global__ void __launch_bounds__(256, 2)
flash_attn() {
    extern __shared__ __half sh[];
    __half* Qs = sh;                       // [128][72]
    __half* Ks = Qs + 128 * AST;           // [2][64][72]   [key][d]
    __half* Vs = Ks + 2 * 64 * AST;        // [2][64][72]   [key][d]
    __half* Ps = Vs + 2 * 64 * AST;        // [8][16][72]   per-warp P

    int t = threadIdx.x, w = t >> 5, lane = t & 31;
    int lm = lane >> 2, lk = lane & 3;
    int bh = blockIdx.y;
    int qb = blockIdx.x * 128;
    size_t base = (size_t)bh * S_ * HD_;

    int rowg = t >> 3;   // 0..31
    int chk  = t & 7;    // 0..7  (8 x 16B chunks per 64-half row)

    // Q: 128 rows (already scaled by 1/8 in the projection epilogue)
#pragma unroll
    for (int i = 0; i < 4; i++) {
        int r = rowg + i * 32;
        cpasync16(s2u(&Qs[r * AST + chk * 8]),
                  g_q + base + (size_t)(qb + r) * HD_ + chk * 8);
    }
    cp_commit();

    auto issue = [&](int kt, int p) {
#pragma unroll
        for (int i = 0; i < 2; i++) {
            int r = rowg + i * 32;
            cpasync16(s2u(&Ks[(p * 64 + r) * AST + chk * 8]),
                      g_k + base + (size_t)(kt + r) * HD_ + chk * 8);
            cpasync16(s2u(&Vs[(p * 64 + r) * AST + chk * 8]),
                      g_v + base + (size_t)(kt + r) * HD_ + chk * 8);
        }
        cp_commit();
    };

    issue(0, 0);

    float o[8][4];
#pragma unroll
    for (int nt = 0; nt < 8; nt++)
#pragma unroll
        for (int i = 0; i < 4; i++) o[nt][i] = 0.f;
    float m0 = -INFINITY, m1 = -INFINITY, l0 = 0.f, l1 = 0.f;

    __half* Pw = Ps + w * 16 * PST;
    int r = w * 16 + lm;

    const int NT = S_ / 64;
    for (int it = 0; it < NT; it++) {
        int p = it & 1;
        cp_wait0();
        __syncthreads();
        if (it + 1 < NT) issue((it + 1) * 64, 1 - p);

        const __half* Kb = Ks + p * 64 * AST;
        const __half* Vb = Vs + p * 64 * AST;

        // S = Q K^T  (16 q-rows x 64 keys per warp, 4 k16 steps over d)
        float sacc[8][4];
#pragma unroll
        for (int nt = 0; nt < 8; nt++)
#pragma unroll
            for (int i = 0; i < 4; i++) sacc[nt][i] = 0.f;

#pragma unroll
        for (int ks = 0; ks < 4; ks++) {
            int kb = ks * 16;
            uint32_t a[4];
            a[0] = *(const uint32_t*)&Qs[(r    ) * AST + kb + 2 * lk    ];
            a[1] = *(const uint32_t*)&Qs[(r + 8) * AST + kb + 2 * lk    ];
            a[2] = *(const uint32_t*)&Qs[(r    ) * AST + kb + 2 * lk + 8];
            a[3] = *(const uint32_t*)&Qs[(r + 8) * AST + kb + 2 * lk + 8];
#pragma unroll
            for (int nt = 0; nt < 8; nt++) {
                int n = nt * 8 + lm;
                uint32_t bb[2];
                bb[0] = *(const uint32_t*)&Kb[n * AST + kb + 2 * lk    ];
                bb[1] = *(const uint32_t*)&Kb[n * AST + kb + 2 * lk + 8];
                mma_f16(sacc[nt], a, bb);
            }
        }

        // Online softmax (rows lm, lm+8; 4 lanes per row -> xor 1,2)
        float mx0 = -INFINITY, mx1 = -INFINITY;
#pragma unroll
        for (int nt = 0; nt < 8; nt++) {
            mx0 = fmaxf(mx0, fmaxf(sacc[nt][0], sacc[nt][1]));
            mx1 = fmaxf(mx1, fmaxf(sacc[nt][2], sacc[nt][3]));
        }
        mx0 = fmaxf(mx0, __shfl_xor_sync(0xffffffffu, mx0, 1));
        mx0 = fmaxf(mx0, __shfl_xor_sync(0xffffffffu, mx0, 2));
        mx1 = fmaxf(mx1, __shfl_xor_sync(0xffffffffu, mx1, 1));
        mx1 = fmaxf(mx1, __shfl_xor_sync(0xffffffffu, mx1, 2));

        float nm0 = fmaxf(m0, mx0), nm1 = fmaxf(m1, mx1);
        float sc0 = __expf(m0 - nm0), sc1 = __expf(m1 - nm1);
        float rs0 = 0.f, rs1 = 0.f;
#pragma unroll
        for (int nt = 0; nt < 8; nt++) {
            sacc[nt][0] = __expf(sacc[nt][0] - nm0);
            sacc[nt][1] = __expf(sacc[nt][1] - nm0);
            sacc[nt][2] = __expf(sacc[nt][2] - nm1);
            sacc[nt][3] = __expf(sacc[nt][3] - nm1);
            rs0 += sacc[nt][0] + sacc[nt][1];
            rs1 += sacc[nt][2] + sacc[nt][3];
        }
        rs0 += __shfl_xor_sync(0xffffffffu, rs0, 1);
        rs0 += __shfl_xor_sync(0xffffffffu, rs0, 2);
        rs1 += __shfl_xor_sync(0xffffffffu, rs1, 1);
        rs1 += __shfl_xor_sync(0xffffffffu, rs1, 2);

        l0 = l0 * sc0 + rs0;  l1 = l1 * sc1 + rs1;
        m0 = nm0;             m1 = nm1;
#pragma unroll
        for (int nt = 0; nt < 8; nt++) {
            o[nt][0] *= sc0; o[nt][1] *= sc0;
            o[nt][2] *= sc1; o[nt][3] *= sc1;
        }

        // P (C-frag) -> per-warp smem, plain row-major fp16 [qrow][key]
#pragma unroll
        for (int nt = 0; nt < 8; nt++) {
            int kc = nt * 8 + 2 * lk;
            Pw[(lm    ) * PST + kc    ] = __float2half_rn(sacc[nt][0]);
            Pw[(lm    ) * PST + kc + 1] = __float2half_rn(sacc[nt][1]);
            Pw[(lm + 8) * PST + kc    ] = __float2half_rn(sacc[nt][2]);
            Pw[(lm + 8) * PST + kc + 1] = __float2half_rn(sacc[nt][3]);
        }
        __syncwarp();

        // O += P V  (A from Pw row-major; B from V[key][d] via scalar pack)
#pragma unroll
        for (int ks = 0; ks < 4; ks++) {
            int kb = ks * 16;
            uint32_t a[4];
            a[0] = *(const uint32_t*)&Pw[(lm    ) * PST + kb + 2 * lk    ];
            a[1] = *(const uint32_t*)&Pw[(lm + 8) * PST + kb + 2 * lk    ];
            a[2] = *(const uint32_t*)&Pw[(lm    ) * PST + kb + 2 * lk + 8];
            a[3] = *(const uint32_t*)&Pw[(lm + 8) * PST + kb + 2 * lk + 8];
#pragma unroll
            for (int nt = 0; nt < 8; nt++) {
                int n = nt * 8 + lm;     // d index
                __half2 h0 = __halves2half2(Vb[(kb + 2 * lk    ) * AST + n],
                                            Vb[(kb + 2 * lk + 1) * AST + n]);
                __half2 h1 = __halves2half2(Vb[(kb + 2 * lk + 8) * AST + n],
                                            Vb[(kb + 2 * lk + 9) * AST + n]);
                uint32_t bb[2];
                bb[0] = *(uint32_t*)&h0;
                bb[1] = *(uint32_t*)&h1;
                mma_f16(o[nt], a, bb);
            }
        }
        __syncwarp();
    }

    // Epilogue: normalize, write ctx[B,S,D] fp16
    float inv0 = 1.f / l0, inv1 = 1.f / l1;
    int b = bh / H_, h = bh - b * H_;
    int srow = qb + w * 16 + lm;
#pragma unroll
    for (int nt = 0; nt < 8; nt++) {
        int col = h * HD_ + nt * 8 + 2 * lk;
        __half2* p0 = (__half2*)&g_ctx[((size_t)b * S_ + srow    ) * D_ + col];
        __half2* p1 = (__half2*)&g_ctx[((size_t)b * S_ + srow + 8) * D_ + col];
        *p0 = __floats2half2_rn(o[nt][0] * inv0, o[nt][1] * inv0);
        *p1 = __floats2half2_rn(o[nt][2] * inv1, o[nt][3] * inv1);
    }
}

// ---------------------------------------------------------------------------
// Launch
// ---------------------------------------------------------------------------
extern "C" void kernel_launch(void* const* d_in, const int* in_sizes, int n_in,
                              void* d_out, int out_size) {
    (void)in_sizes; (void)n_in; (void)out_size;
    const float* x  = (const float*)d_in[0];
    const float* Wq = (const float*)d_in[1];
    const float* bq = (const float*)d_in[2];
    const float* Wk = (const float*)d_in[3];
    const float* bk = (const float*)d_in[4];
    const float* Wv = (const float*)d_in[5];
    const float* bv = (const float*)d_in[6];
    const float* Wo = (const float*)d_in[7];
    const float* bo = (const float*)d_in[8];
    float* out = (float*)d_out;

    __half *xt, *q, *k, *v, *ctx, *wqkv, *wo;
    cudaGetSymbolAddress((void**)&xt,   g_xt);
    cudaGetSymbolAddress((void**)&q,    g_q);
    cudaGetSymbolAddress((void**)&k,    g_k);
    cudaGetSymbolAddress((void**)&v,    g_v);
    cudaGetSymbolAddress((void**)&ctx,  g_ctx);
    cudaGetSymbolAddress((void**)&wqkv, g_wqkv);
    cudaGetSymbolAddress((void**)&wo,   g_wo);

    cudaFuncSetAttribute(flash_attn, cudaFuncAttributeMaxDynamicSharedMemorySize,
                         ATTN_SMEM_BYTES);

    // 0) weights -> fp16 scratch
    weight_prep<<<(D_ * D_ / 4 + 255) / 256, 256>>>(Wq, Wk, Wv, Wo);
    // 1) PE table
    pe_kernel<<<(D_ * S_ + 255) / 256, 256>>>();
    // 2) x + PE -> xt[B,S,D] fp16
    addpe_transpose<<<dim3(S_ / 32, D_ / 32, B_), dim3(32, 8)>>>(x);
    // 3) fused QKV projection (N=3072) -> q,k,v all [BH][S][hd] fp16
    gemm_f16<1><<<dim3(3 * D_ / 128, BS_ / 128), 256>>>(
        xt, wqkv, bq, bk, bv, q, k, v, D_);
    // 4) attention -> ctx[B,S,D] fp16
    flash_attn<<<dim3(S_ / 128, B_ * H_), 256, ATTN_SMEM_BYTES>>>();
    // 5) output projection -> [B,D,S] fp32
    gemm_f16<2><<<dim3(D_ / 128, BS_ / 128), 256>>>(
        ctx, wo, bo, nullptr, nullptr, out, nullptr, nullptr, D_);
}

// round 10
// speedup vs baseline: 2.8415x; 1.0604x over previous
#include <cuda_runtime.h>
#include <cuda_fp16.h>
#include <cstdint>
#include <math.h>

// Problem constants
#define B_  4
#define D_  1024
#define S_  2048
#define H_  16
#define HD_ 64
#define BS_ (B_*S_)

// ---------------------------------------------------------------------------
// Scratch (static device globals — no allocation allowed)
// ---------------------------------------------------------------------------
__device__ float  g_pe  [D_*S_];             // positional encoding [D][S]
__device__ __half g_xt  [BS_*(size_t)D_];    // x+PE, [B,S,D]  fp16
__device__ __half g_q   [BS_*(size_t)D_];    // Q/8  [BH][S][hd] fp16
__device__ __half g_k   [BS_*(size_t)D_];    // K    [BH][S][hd] fp16
__device__ __half g_v   [BS_*(size_t)D_];    // V    [BH][S][hd] fp16
__device__ __half g_ctx [BS_*(size_t)D_];    // attention out [B,S,D] fp16
__device__ __half g_wqkv[3*D_*(size_t)D_];   // Wq|Wk|Wv stacked [3072][1024] fp16
__device__ __half g_wo  [D_*(size_t)D_];     // Wo fp16

// ---------------------------------------------------------------------------
// Helpers
// ---------------------------------------------------------------------------
__device__ __forceinline__ uint32_t s2u(const void* p) {
    return (uint32_t)__cvta_generic_to_shared(p);
}
__device__ __forceinline__ void cpasync16(uint32_t dst, const void* src) {
    asm volatile("cp.async.ca.shared.global [%0], [%1], 16;\n" :: "r"(dst), "l"(src));
}
__device__ __forceinline__ void cp_commit() {
    asm volatile("cp.async.commit_group;\n");
}
__device__ __forceinline__ void cp_wait0() {
    asm volatile("cp.async.wait_group 0;\n");
}

// fp16 mma: m16n8k16, fp32 accumulate
__device__ __forceinline__ void mma_f16(float* c, const uint32_t* a, const uint32_t* b) {
    asm volatile(
        "mma.sync.aligned.m16n8k16.row.col.f32.f16.f16.f32 "
        "{%0,%1,%2,%3}, {%4,%5,%6,%7}, {%8,%9}, {%0,%1,%2,%3};\n"
        : "+f"(c[0]), "+f"(c[1]), "+f"(c[2]), "+f"(c[3])
        : "r"(a[0]), "r"(a[1]), "r"(a[2]), "r"(a[3]), "r"(b[0]), "r"(b[1]));
}

__device__ __forceinline__ uint32_t packh2(float x, float y) {
    __half2 h = __floats2half2_rn(x, y);
    return *reinterpret_cast<uint32_t*>(&h);
}

__device__ __forceinline__ void ldsm_x4(uint32_t& r0, uint32_t& r1, uint32_t& r2,
                                        uint32_t& r3, uint32_t addr) {
    asm volatile("ldmatrix.sync.aligned.m8n8.x4.shared.b16 {%0,%1,%2,%3}, [%4];"
                 : "=r"(r0), "=r"(r1), "=r"(r2), "=r"(r3) : "r"(addr));
}
__device__ __forceinline__ void ldsm_x4_t(uint32_t& r0, uint32_t& r1, uint32_t& r2,
                                          uint32_t& r3, uint32_t addr) {
    asm volatile("ldmatrix.sync.aligned.m8n8.x4.trans.shared.b16 {%0,%1,%2,%3}, [%4];"
                 : "=r"(r0), "=r"(r1), "=r"(r2), "=r"(r3) : "r"(addr));
}

// ---------------------------------------------------------------------------
// 0) Weight prep: convert weights to fp16 (Wq|Wk|Wv stacked, Wo)
// ---------------------------------------------------------------------------
__global__ void weight_prep(const float* __restrict__ Wq, const float* __restrict__ Wk,
                            const float* __restrict__ Wv, const float* __restrict__ Wo) {
    int idx4 = blockIdx.x * blockDim.x + threadIdx.x;
    const int NW = D_ * D_ / 4;
    if (idx4 >= NW) return;
    float4 a = ((const float4*)Wq)[idx4];
    float4 b = ((const float4*)Wk)[idx4];
    float4 c = ((const float4*)Wv)[idx4];
    float4 d = ((const float4*)Wo)[idx4];
    __half2* wq2 = (__half2*)g_wqkv;
    __half2* wo2 = (__half2*)g_wo;
    wq2[2*idx4    ]        = __floats2half2_rn(a.x, a.y);
    wq2[2*idx4 + 1]        = __floats2half2_rn(a.z, a.w);
    wq2[2*(idx4+NW)    ]   = __floats2half2_rn(b.x, b.y);
    wq2[2*(idx4+NW) + 1]   = __floats2half2_rn(b.z, b.w);
    wq2[2*(idx4+2*NW)    ] = __floats2half2_rn(c.x, c.y);
    wq2[2*(idx4+2*NW) + 1] = __floats2half2_rn(c.z, c.w);
    wo2[2*idx4    ]        = __floats2half2_rn(d.x, d.y);
    wo2[2*idx4 + 1]        = __floats2half2_rn(d.z, d.w);
}

// ---------------------------------------------------------------------------
// 1) Positional encoding table (double trig for exact fp32 match)
// ---------------------------------------------------------------------------
__global__ void pe_kernel() {
    int idx = blockIdx.x * blockDim.x + threadIdx.x;
    if (idx >= D_ * S_) return;
    int d = idx / S_;
    int s = idx - d * S_;
    double freq_d = exp((double)(d & ~1) * (-9.210340371976184 / (double)D_));
    float  freq   = (float)freq_d;
    float  ang    = (float)s * freq;
    float  val    = (d & 1) ? (float)cos((double)ang) : (float)sin((double)ang);
    g_pe[idx] = val;
}

// ---------------------------------------------------------------------------
// 2) x[B,D,S] + pe[D,S]  ->  xt[B,S,D]  fp16
// ---------------------------------------------------------------------------
__global__ void addpe_transpose(const float* __restrict__ x) {
    __shared__ float tile[32][33];
    int b  = blockIdx.z;
    int d0 = blockIdx.y * 32;
    int s0 = blockIdx.x * 32;
    int tx = threadIdx.x, ty = threadIdx.y;  // (32, 8)
#pragma unroll
    for (int j = 0; j < 4; j++) {
        int d = d0 + ty + j * 8;
        tile[ty + j * 8][tx] = x[((size_t)b * D_ + d) * S_ + s0 + tx]
                             + g_pe[(size_t)d * S_ + s0 + tx];
    }
    __syncthreads();
#pragma unroll
    for (int j = 0; j < 4; j++) {
        int s = s0 + ty + j * 8;
        g_xt[((size_t)b * S_ + s) * D_ + d0 + tx] =
            __float2half_rn(tile[tx][ty + j * 8]);
    }
}

// ---------------------------------------------------------------------------
// 3/5) fp16 GEMM:  C[M,N] = A[M,K] @ W[N,K]^T + bias.
//      CTA tile 128x256, BK=32, 256 thr (8 warps, 2x4), WARP TILE 64x64
//      (halves fragment-LDS wavefronts per flop vs 32x64).
//      Smem [row][k] half, stride 40, cp.async double-buffered (dynamic).
// MODE 1: fused QKV (N=3072): Q scaled 1/8; Q/K/V all -> [BH][S][hd] fp16.
// MODE 2: O-proj: output fp32 transposed to [B,D,S].
// ---------------------------------------------------------------------------
#define GST 40   // halves per smem row
#define GEMM_SMEM ((2*128*GST + 2*256*GST) * 2)   // 61440 B

template <int MODE>
__global__ void __launch_bounds__(256, 1)
gemm_f16(const __half* __restrict__ A, const __half* __restrict__ W,
         const float* __restrict__ b0p, const float* __restrict__ b1p,
         const float* __restrict__ b2p,
         void* __restrict__ C0v, void* __restrict__ C1v, void* __restrict__ C2v,
         int K) {
    extern __shared__ __half gsm[];
    __half* As = gsm;                       // [2][128][GST]
    __half* Bs = gsm + 2 * 128 * GST;       // [2][256][GST]

    int t    = threadIdx.x;
    int wid  = t >> 5, lane = t & 31;
    int lm   = lane >> 2, lk = lane & 3;
    int wm   = (wid >> 2) * 64;             // 0 or 64
    int wn   = (wid & 3) * 64;              // 0..192
    int bm   = blockIdx.y * 128;
    int bn   = blockIdx.x * 256;

    float c[4][8][4];
#pragma unroll
    for (int mt = 0; mt < 4; mt++)
#pragma unroll
        for (int nt = 0; nt < 8; nt++)
#pragma unroll
            for (int i = 0; i < 4; i++) c[mt][nt][i] = 0.f;

    auto issue = [&](int k0, int p) {
#pragma unroll
        for (int i = 0; i < 2; i++) {       // A: 512 chunks
            int ci = t + i * 256;
            int r = ci >> 2, ch = ci & 3;
            cpasync16(s2u(&As[(p * 128 + r) * GST + ch * 8]),
                      A + (size_t)(bm + r) * K + k0 + ch * 8);
        }
#pragma unroll
        for (int i = 0; i < 4; i++) {       // B: 1024 chunks
            int ci = t + i * 256;
            int r = ci >> 2, ch = ci & 3;
            cpasync16(s2u(&Bs[(p * 256 + r) * GST + ch * 8]),
                      W + (size_t)(bn + r) * K + k0 + ch * 8);
        }
        cp_commit();
    };

    int NT = K >> 5;
    issue(0, 0);

    for (int it = 0; it < NT; it++) {
        int p = it & 1;
        cp_wait0();
        __syncthreads();
        if (it + 1 < NT) issue((it + 1) << 5, 1 - p);

        const __half* Ab = As + p * 128 * GST;
        const __half* Bb = Bs + p * 256 * GST;
#pragma unroll
        for (int ks = 0; ks < 2; ks++) {
            int kb = ks * 16;
            uint32_t a[4][4];
#pragma unroll
            for (int mt = 0; mt < 4; mt++) {
                int r = wm + mt * 16 + lm;
                a[mt][0] = *(const uint32_t*)&Ab[(r    ) * GST + kb + 2 * lk    ];
                a[mt][1] = *(const uint32_t*)&Ab[(r + 8) * GST + kb + 2 * lk    ];
                a[mt][2] = *(const uint32_t*)&Ab[(r    ) * GST + kb + 2 * lk + 8];
                a[mt][3] = *(const uint32_t*)&Ab[(r + 8) * GST + kb + 2 * lk + 8];
            }
            uint32_t bf[8][2];
#pragma unroll
            for (int nt = 0; nt < 8; nt++) {
                int cn = wn + nt * 8 + lm;
                bf[nt][0] = *(const uint32_t*)&Bb[cn * GST + kb + 2 * lk    ];
                bf[nt][1] = *(const uint32_t*)&Bb[cn * GST + kb + 2 * lk + 8];
            }
#pragma unroll
            for (int mt = 0; mt < 4; mt++)
#pragma unroll
                for (int nt = 0; nt < 8; nt++)
                    mma_f16(c[mt][nt], a[mt], bf[nt]);
        }
        __syncthreads();
    }

    // Epilogue
    int which = bn >> 10;       // MODE 1: 0=Q 1=K 2=V (uniform per CTA; 1024%256==0)
    int cc0   = bn & 1023;
    float scale = (MODE == 1 && which == 0) ? 0.125f : 1.0f;
#pragma unroll
    for (int mt = 0; mt < 4; mt++) {
        int r0 = bm + wm + mt * 16 + lm;
        int b  = r0 / S_;
        int s  = r0 - b * S_;
#pragma unroll
        for (int nt = 0; nt < 8; nt++) {
            int col = wn + nt * 8 + 2 * lk;
            if (MODE == 1) {
                int cc = cc0 + col;
                const float* bias = (which == 0) ? b0p : (which == 1) ? b1p : b2p;
                __half* C = (which == 0) ? (__half*)C0v
                          : (which == 1) ? (__half*)C1v : (__half*)C2v;
                float bv0 = bias[cc], bv1 = bias[cc + 1];
                float v00 = (c[mt][nt][0] + bv0) * scale;
                float v01 = (c[mt][nt][1] + bv1) * scale;
                float v10 = (c[mt][nt][2] + bv0) * scale;
                float v11 = (c[mt][nt][3] + bv1) * scale;
                int h  = cc >> 6;
                int hd = cc & 63;
                __half2* p0 = (__half2*)&C[(((size_t)(b * H_ + h)) * S_ + s    ) * HD_ + hd];
                __half2* p1 = (__half2*)&C[(((size_t)(b * H_ + h)) * S_ + s + 8) * HD_ + hd];
                *p0 = __floats2half2_rn(v00, v01);
                *p1 = __floats2half2_rn(v10, v11);
            } else {            // O-proj: fp32 transposed [B,D,S]
                int gcol = bn + col;
                float* C = (float*)C0v;
                float bv0 = b0p[gcol], bv1 = b0p[gcol + 1];
                C[((size_t)b * D_ + gcol    ) * S_ + s    ] = c[mt][nt][0] + bv0;
                C[((size_t)b * D_ + gcol + 1) * S_ + s    ] = c[mt][nt][1] + bv1;
                C[((size_t)b * D_ + gcol    ) * S_ + s + 8] = c[mt][nt][2] + bv0;
                C[((size_t)b * D_ + gcol + 1) * S_ + s + 8] = c[mt][nt][3] + bv1;
            }
        }
    }
}

// ---------------------------------------------------------------------------
// 4) Flash attention, fp16 mma + ldmatrix.  Grid (S/128, B*H), 256 thr.
//    Q/K/V smem [row][d]; fragments via ldmatrix.x4; V via ldmatrix.x4.trans
//    (hardware transpose of the [key][d] tile -> PV B-fragments, no scalar
//    packing).  P through per-warp smem with packed STS.32.
// ---------------------------------------------------------------------------
#define AST 72   // halves per smem row: 144B stride -> ldmatrix conflict-free
#define PST 72
#define ATTN_SMEM_BYTES ((128*AST + 2*64*AST + 2*64*AST + 8*16*PST) * 2)  // 73728

__global__ void __launch_bounds__(256, 2)
flash_attn() {
    extern __shared__ __half sh[];
    __half* Qs = sh;                       // [128][72]
    __half* Ks = Qs + 128 * AST;           // [2][64][72]   [key][d]
    __half* Vs = Ks + 2 * 64 * AST;        // [2][64][72]   [key][d]
    __half* Ps = Vs + 2 * 64 * AST;        // [8][16][72]   per-warp P

    int t = threadIdx.x, w = t >> 5, lane = t & 31;
    int lm = lane >> 2, lk = lane & 3;
    int bh = blockIdx.y;
    int qb = blockIdx.x * 128;
    size_t base = (size_t)bh * S_ * HD_;

    int rowg = t >> 3;   // 0..31
    int chk  = t & 7;    // 0..7

    // ldmatrix lane-address components
    int l15 = lane & 15;          // row within 16-row block
    int lhi = (lane >> 4) * 8;    // +8 k-offset for upper two tiles

#pragma unroll
    for (int i = 0; i < 4; i++) {
        int r = rowg + i * 32;
        cpasync16(s2u(&Qs[r * AST + chk * 8]),
                  g_q + base + (size_t)(qb + r) * HD_ + chk * 8);
    }
    cp_commit();

    auto issue = [&](int kt, int p) {
#pragma unroll
        for (int i = 0; i < 2; i++) {
            int r = rowg + i * 32;
            cpasync16(s2u(&Ks[(p * 64 + r) * AST + chk * 8]),
                      g_k + base + (size_t)(kt + r) * HD_ + chk * 8);
            cpasync16(s2u(&Vs[(p * 64 + r) * AST + chk * 8]),
                      g_v + base + (size_t)(kt + r) * HD_ + chk * 8);
        }
        cp_commit();
    };

    issue(0, 0);

    float o[8][4];
#pragma unroll
    for (int nt = 0; nt < 8; nt++)
#pragma unroll
        for (int i = 0; i < 4; i++) o[nt][i] = 0.f;
    float m0 = -INFINITY, m1 = -INFINITY, l0 = 0.f, l1 = 0.f;

    __half* Pw = Ps + w * 16 * PST;

    const int NT = S_ / 64;
    for (int it = 0; it < NT; it++) {
        int p = it & 1;
        cp_wait0();
        __syncthreads();
        if (it + 1 < NT) issue((it + 1) * 64, 1 - p);

        const __half* Kb = Ks + p * 64 * AST;
        const __half* Vb = Vs + p * 64 * AST;

        // S = Q K^T
        float sacc[8][4];
#pragma unroll
        for (int nt = 0; nt < 8; nt++)
#pragma unroll
            for (int i = 0; i < 4; i++) sacc[nt][i] = 0.f;

#pragma unroll
        for (int ks = 0; ks < 4; ks++) {
            int kb = ks * 16;
            uint32_t a[4];
            // A-frag: tiles (rows w*16+0..7 / +8..15) x (kb / kb+8)
            ldsm_x4(a[0], a[1], a[2], a[3],
                    s2u(&Qs[(w * 16 + l15) * AST + kb + lhi]));
            uint32_t bf[8][2];
#pragma unroll
            for (int j = 0; j < 4; j++) {
                // B-frag pair: tiles (n=2j*8.. / (2j+1)*8..) x (kb / kb+8)
                int g = lane >> 3;
                int nrow = (2 * j + (g >> 1)) * 8 + (lane & 7);
                int ncol = kb + (g & 1) * 8;
                ldsm_x4(bf[2*j][0], bf[2*j][1], bf[2*j+1][0], bf[2*j+1][1],
                        s2u(&Kb[nrow * AST + ncol]));
            }
#pragma unroll
            for (int nt = 0; nt < 8; nt++)
                mma_f16(sacc[nt], a, bf[nt]);
        }

        // Online softmax (rows lm, lm+8)
        float mx0 = -INFINITY, mx1 = -INFINITY;
#pragma unroll
        for (int nt = 0; nt < 8; nt++) {
            mx0 = fmaxf(mx0, fmaxf(sacc[nt][0], sacc[nt][1]));
            mx1 = fmaxf(mx1, fmaxf(sacc[nt][2], sacc[nt][3]));
        }
        mx0 = fmaxf(mx0, __shfl_xor_sync(0xffffffffu, mx0, 1));
        mx0 = fmaxf(mx0, __shfl_xor_sync(0xffffffffu, mx0, 2));
        mx1 = fmaxf(mx1, __shfl_xor_sync(0xffffffffu, mx1, 1));
        mx1 = fmaxf(mx1, __shfl_xor_sync(0xffffffffu, mx1, 2));

        float nm0 = fmaxf(m0, mx0), nm1 = fmaxf(m1, mx1);
        float sc0 = __expf(m0 - nm0), sc1 = __expf(m1 - nm1);
        float rs0 = 0.f, rs1 = 0.f;
#pragma unroll
        for (int nt = 0; nt < 8; nt++) {
            sacc[nt][0] = __expf(sacc[nt][0] - nm0);
            sacc[nt][1] = __expf(sacc[nt][1] - nm0);
            sacc[nt][2] = __expf(sacc[nt][2] - nm1);
            sacc[nt][3] = __expf(sacc[nt][3] - nm1);
            rs0 += sacc[nt][0] + sacc[nt][1];
            rs1 += sacc[nt][2] + sacc[nt][3];
        }
        rs0 += __shfl_xor_sync(0xffffffffu, rs0, 1);
        rs0 += __shfl_xor_sync(0xffffffffu, rs0, 2);
        rs1 += __shfl_xor_sync(0xffffffffu, rs1, 1);
        rs1 += __shfl_xor_sync(0xffffffffu, rs1, 2);

        l0 = l0 * sc0 + rs0;  l1 = l1 * sc1 + rs1;
        m0 = nm0;             m1 = nm1;
#pragma unroll
        for (int nt = 0; nt < 8; nt++) {
            o[nt][0] *= sc0; o[nt][1] *= sc0;
            o[nt][2] *= sc1; o[nt][3] *= sc1;
        }

        // P (C-frag) -> per-warp smem, packed STS.32 (conflict-free)
#pragma unroll
        for (int nt = 0; nt < 8; nt++) {
            int kc = nt * 8 + 2 * lk;
            *(uint32_t*)&Pw[(lm    ) * PST + kc] = packh2(sacc[nt][0], sacc[nt][1]);
            *(uint32_t*)&Pw[(lm + 8) * PST + kc] = packh2(sacc[nt][2], sacc[nt][3]);
        }
        __syncwarp();

        // O += P V   (A-frags: ldmatrix on Pw; B-frags: ldmatrix.trans on V)
#pragma unroll
        for (int ks = 0; ks < 4; ks++) {
            int kb = ks * 16;
            uint32_t a[4];
            ldsm_x4(a[0], a[1], a[2], a[3],
                    s2u(&Pw[l15 * PST + kb + lhi]));
#pragma unroll
            for (int j = 0; j < 4; j++) {
                // V tiles: rows (keys) kb+(lane&15), cols d = (2j + lane>>4)*8
                uint32_t b0, b1, b2, b3;
                int vrow = kb + l15;
                int vcol = (2 * j) * 8 + lhi;
                ldsm_x4_t(b0, b1, b2, b3, s2u(&Vb[vrow * AST + vcol]));
                uint32_t bb0[2] = {b0, b1};
                uint32_t bb1[2] = {b2, b3};
                mma_f16(o[2*j    ], a, bb0);
                mma_f16(o[2*j + 1], a, bb1);
            }
        }
        __syncwarp();
    }

    // Epilogue: normalize, write ctx[B,S,D] fp16
    float inv0 = 1.f / l0, inv1 = 1.f / l1;
    int b = bh / H_, h = bh - b * H_;
    int srow = qb + w * 16 + lm;
#pragma unroll
    for (int nt = 0; nt < 8; nt++) {
        int col = h * HD_ + nt * 8 + 2 * lk;
        __half2* p0 = (__half2*)&g_ctx[((size_t)b * S_ + srow    ) * D_ + col];
        __half2* p1 = (__half2*)&g_ctx[((size_t)b * S_ + srow + 8) * D_ + col];
        *p0 = __floats2half2_rn(o[nt][0] * inv0, o[nt][1] * inv0);
        *p1 = __floats2half2_rn(o[nt][2] * inv1, o[nt][3] * inv1);
    }
}

// ---------------------------------------------------------------------------
// Launch
// ---------------------------------------------------------------------------
extern "C" void kernel_launch(void* const* d_in, const int* in_sizes, int n_in,
                              void* d_out, int out_size) {
    (void)in_sizes; (void)n_in; (void)out_size;
    const float* x  = (const float*)d_in[0];
    const float* Wq = (const float*)d_in[1];
    const float* bq = (const float*)d_in[2];
    const float* Wk = (const float*)d_in[3];
    const float* bk = (const float*)d_in[4];
    const float* Wv = (const float*)d_in[5];
    const float* bv = (const float*)d_in[6];
    const float* Wo = (const float*)d_in[7];
    const float* bo = (const float*)d_in[8];
    float* out = (float*)d_out;

    __half *xt, *q, *k, *v, *ctx, *wqkv, *wo;
    cudaGetSymbolAddress((void**)&xt,   g_xt);
    cudaGetSymbolAddress((void**)&q,    g_q);
    cudaGetSymbolAddress((void**)&k,    g_k);
    cudaGetSymbolAddress((void**)&v,    g_v);
    cudaGetSymbolAddress((void**)&ctx,  g_ctx);
    cudaGetSymbolAddress((void**)&wqkv, g_wqkv);
    cudaGetSymbolAddress((void**)&wo,   g_wo);

    cudaFuncSetAttribute(gemm_f16<1>, cudaFuncAttributeMaxDynamicSharedMemorySize,
                         GEMM_SMEM);
    cudaFuncSetAttribute(gemm_f16<2>, cudaFuncAttributeMaxDynamicSharedMemorySize,
                         GEMM_SMEM);
    cudaFuncSetAttribute(flash_attn, cudaFuncAttributeMaxDynamicSharedMemorySize,
                         ATTN_SMEM_BYTES);

    // 0) weights -> fp16 scratch
    weight_prep<<<(D_ * D_ / 4 + 255) / 256, 256>>>(Wq, Wk, Wv, Wo);
    // 1) PE table
    pe_kernel<<<(D_ * S_ + 255) / 256, 256>>>();
    // 2) x + PE -> xt[B,S,D] fp16
    addpe_transpose<<<dim3(S_ / 32, D_ / 32, B_), dim3(32, 8)>>>(x);
    // 3) fused QKV projection (N=3072) -> q,k,v all [BH][S][hd] fp16
    gemm_f16<1><<<dim3(3 * D_ / 256, BS_ / 128), 256, GEMM_SMEM>>>(
        xt, wqkv, bq, bk, bv, q, k, v, D_);
    // 4) attention -> ctx[B,S,D] fp16
    flash_attn<<<dim3(S_ / 128, B_ * H_), 256, ATTN_SMEM_BYTES>>>();
    // 5) output projection -> [B,D,S] fp32
    gemm_f16<2><<<dim3(D_ / 256, BS_ / 128), 256, GEMM_SMEM>>>(
        ctx, wo, bo, nullptr, nullptr, out, nullptr, nullptr, D_);
}

// round 11
// speedup vs baseline: 3.1219x; 1.0987x over previous
#include <cuda_runtime.h>
#include <cuda_fp16.h>
#include <cstdint>
#include <math.h>

// Problem constants
#define B_  4
#define D_  1024
#define S_  2048
#define H_  16
#define HD_ 64
#define BS_ (B_*S_)

// ---------------------------------------------------------------------------
// Scratch (static device globals — no allocation allowed)
// ---------------------------------------------------------------------------
__device__ float  g_pe  [D_*S_];             // positional encoding [D][S]
__device__ __half g_xt  [BS_*(size_t)D_];    // x+PE, [B,S,D]  fp16
__device__ __half g_q   [BS_*(size_t)D_];    // Q/8  [BH][S][hd] fp16
__device__ __half g_k   [BS_*(size_t)D_];    // K    [BH][S][hd] fp16
__device__ __half g_v   [BS_*(size_t)D_];    // V    [BH][S][hd] fp16
__device__ __half g_ctx [BS_*(size_t)D_];    // attention out [B,S,D] fp16
__device__ __half g_wqkv[3*D_*(size_t)D_];   // Wq|Wk|Wv stacked [3072][1024] fp16
__device__ __half g_wo  [D_*(size_t)D_];     // Wo fp16

// ---------------------------------------------------------------------------
// Helpers
// ---------------------------------------------------------------------------
__device__ __forceinline__ uint32_t s2u(const void* p) {
    return (uint32_t)__cvta_generic_to_shared(p);
}
__device__ __forceinline__ void cpasync16(uint32_t dst, const void* src) {
    asm volatile("cp.async.ca.shared.global [%0], [%1], 16;\n" :: "r"(dst), "l"(src));
}
__device__ __forceinline__ void cp_commit() {
    asm volatile("cp.async.commit_group;\n");
}
__device__ __forceinline__ void cp_wait0() {
    asm volatile("cp.async.wait_group 0;\n");
}
__device__ __forceinline__ void cp_wait1() {
    asm volatile("cp.async.wait_group 1;\n");
}

// fp16 mma: m16n8k16, fp32 accumulate
__device__ __forceinline__ void mma_f16(float* c, const uint32_t* a, const uint32_t* b) {
    asm volatile(
        "mma.sync.aligned.m16n8k16.row.col.f32.f16.f16.f32 "
        "{%0,%1,%2,%3}, {%4,%5,%6,%7}, {%8,%9}, {%0,%1,%2,%3};\n"
        : "+f"(c[0]), "+f"(c[1]), "+f"(c[2]), "+f"(c[3])
        : "r"(a[0]), "r"(a[1]), "r"(a[2]), "r"(a[3]), "r"(b[0]), "r"(b[1]));
}

__device__ __forceinline__ uint32_t packh2(float x, float y) {
    __half2 h = __floats2half2_rn(x, y);
    return *reinterpret_cast<uint32_t*>(&h);
}

__device__ __forceinline__ void ldsm_x4(uint32_t& r0, uint32_t& r1, uint32_t& r2,
                                        uint32_t& r3, uint32_t addr) {
    asm volatile("ldmatrix.sync.aligned.m8n8.x4.shared.b16 {%0,%1,%2,%3}, [%4];"
                 : "=r"(r0), "=r"(r1), "=r"(r2), "=r"(r3) : "r"(addr));
}
__device__ __forceinline__ void ldsm_x4_t(uint32_t& r0, uint32_t& r1, uint32_t& r2,
                                          uint32_t& r3, uint32_t addr) {
    asm volatile("ldmatrix.sync.aligned.m8n8.x4.trans.shared.b16 {%0,%1,%2,%3}, [%4];"
                 : "=r"(r0), "=r"(r1), "=r"(r2), "=r"(r3) : "r"(addr));
}

// ---------------------------------------------------------------------------
// 0) Weight prep: convert weights to fp16 (Wq|Wk|Wv stacked, Wo)
// ---------------------------------------------------------------------------
__global__ void weight_prep(const float* __restrict__ Wq, const float* __restrict__ Wk,
                            const float* __restrict__ Wv, const float* __restrict__ Wo) {
    int idx4 = blockIdx.x * blockDim.x + threadIdx.x;
    const int NW = D_ * D_ / 4;
    if (idx4 >= NW) return;
    float4 a = ((const float4*)Wq)[idx4];
    float4 b = ((const float4*)Wk)[idx4];
    float4 c = ((const float4*)Wv)[idx4];
    float4 d = ((const float4*)Wo)[idx4];
    __half2* wq2 = (__half2*)g_wqkv;
    __half2* wo2 = (__half2*)g_wo;
    wq2[2*idx4    ]        = __floats2half2_rn(a.x, a.y);
    wq2[2*idx4 + 1]        = __floats2half2_rn(a.z, a.w);
    wq2[2*(idx4+NW)    ]   = __floats2half2_rn(b.x, b.y);
    wq2[2*(idx4+NW) + 1]   = __floats2half2_rn(b.z, b.w);
    wq2[2*(idx4+2*NW)    ] = __floats2half2_rn(c.x, c.y);
    wq2[2*(idx4+2*NW) + 1] = __floats2half2_rn(c.z, c.w);
    wo2[2*idx4    ]        = __floats2half2_rn(d.x, d.y);
    wo2[2*idx4 + 1]        = __floats2half2_rn(d.z, d.w);
}

// ---------------------------------------------------------------------------
// 1) Positional encoding table (double trig for exact fp32 match)
// ---------------------------------------------------------------------------
__global__ void pe_kernel() {
    int idx = blockIdx.x * blockDim.x + threadIdx.x;
    if (idx >= D_ * S_) return;
    int d = idx / S_;
    int s = idx - d * S_;
    double freq_d = exp((double)(d & ~1) * (-9.210340371976184 / (double)D_));
    float  freq   = (float)freq_d;
    float  ang    = (float)s * freq;
    float  val    = (d & 1) ? (float)cos((double)ang) : (float)sin((double)ang);
    g_pe[idx] = val;
}

// ---------------------------------------------------------------------------
// 2) x[B,D,S] + pe[D,S]  ->  xt[B,S,D]  fp16
// ---------------------------------------------------------------------------
__global__ void addpe_transpose(const float* __restrict__ x) {
    __shared__ float tile[32][33];
    int b  = blockIdx.z;
    int d0 = blockIdx.y * 32;
    int s0 = blockIdx.x * 32;
    int tx = threadIdx.x, ty = threadIdx.y;  // (32, 8)
#pragma unroll
    for (int j = 0; j < 4; j++) {
        int d = d0 + ty + j * 8;
        tile[ty + j * 8][tx] = x[((size_t)b * D_ + d) * S_ + s0 + tx]
                             + g_pe[(size_t)d * S_ + s0 + tx];
    }
    __syncthreads();
#pragma unroll
    for (int j = 0; j < 4; j++) {
        int s = s0 + ty + j * 8;
        g_xt[((size_t)b * S_ + s) * D_ + d0 + tx] =
            __float2half_rn(tile[tx][ty + j * 8]);
    }
}

// ---------------------------------------------------------------------------
// 3/5) fp16 GEMM:  C[M,N] = A[M,K] @ W[N,K]^T + bias.
//      CTA 128x128, BK=32, 256 thr (8 warps 4x2), warp tile 32x64 (R9 shape,
//      2 CTAs/SM), ldmatrix.x4 fragments (4x fewer L1 issue slots), 3-stage
//      cp.async pipeline (wait_group 1 -> compute fully decoupled from the
//      in-flight load).
// MODE 1: fused QKV (N=3072): Q scaled 1/8; Q/K/V all -> [BH][S][hd] fp16.
// MODE 2: O-proj: output fp32 transposed to [B,D,S].
// ---------------------------------------------------------------------------
#define GST 40   // halves per smem row
#define GEMM_SMEM (3 * 2 * 128 * GST * 2)   // 3 stages x (A+B) x 128 x 40 halves = 61440 B

template <int MODE>
__global__ void __launch_bounds__(256, 2)
gemm_f16(const __half* __restrict__ A, const __half* __restrict__ W,
         const float* __restrict__ b0p, const float* __restrict__ b1p,
         const float* __restrict__ b2p,
         void* __restrict__ C0v, void* __restrict__ C1v, void* __restrict__ C2v,
         int K) {
    extern __shared__ __half gsm[];
    __half* As = gsm;                       // [3][128][GST]
    __half* Bs = gsm + 3 * 128 * GST;       // [3][128][GST]

    int t    = threadIdx.x;
    int wid  = t >> 5, lane = t & 31;
    int lm   = lane >> 2, lk = lane & 3;
    int wm   = (wid >> 1) * 32;
    int wn   = (wid & 1) * 64;
    int bm   = blockIdx.y * 128;
    int bn   = blockIdx.x * 128;
    int l15  = lane & 15;
    int lhi  = (lane >> 4) * 8;

    float c[2][8][4];
#pragma unroll
    for (int mt = 0; mt < 2; mt++)
#pragma unroll
        for (int nt = 0; nt < 8; nt++)
#pragma unroll
            for (int i = 0; i < 4; i++) c[mt][nt][i] = 0.f;

    int rowg = t >> 2;        // 0..63
    int chk  = t & 3;         // 0..3

    auto issue = [&](int k0, int st) {
#pragma unroll
        for (int i = 0; i < 2; i++) {
            int r = rowg + i * 64;
            cpasync16(s2u(&As[(st * 128 + r) * GST + chk * 8]),
                      A + (size_t)(bm + r) * K + k0 + chk * 8);
            cpasync16(s2u(&Bs[(st * 128 + r) * GST + chk * 8]),
                      W + (size_t)(bn + r) * K + k0 + chk * 8);
        }
        cp_commit();
    };

    int NT = K >> 5;          // 32
    issue(0, 0);
    issue(32, 1);

    for (int it = 0; it < NT; it++) {
        int st = it % 3;
        if (it == NT - 1) cp_wait0(); else cp_wait1();
        __syncthreads();
        if (it + 2 < NT) issue((it + 2) << 5, (it + 2) % 3);

        const __half* Ab = As + st * 128 * GST;
        const __half* Bb = Bs + st * 128 * GST;
#pragma unroll
        for (int ks = 0; ks < 2; ks++) {
            int kb = ks * 16;
            uint32_t a[2][4];
#pragma unroll
            for (int mt = 0; mt < 2; mt++)
                ldsm_x4(a[mt][0], a[mt][1], a[mt][2], a[mt][3],
                        s2u(&Ab[(wm + mt * 16 + l15) * GST + kb + lhi]));
            uint32_t bf[8][2];
#pragma unroll
            for (int j = 0; j < 4; j++) {
                int g = lane >> 3;
                int nrow = wn + (2 * j + (g >> 1)) * 8 + (lane & 7);
                int ncol = kb + (g & 1) * 8;
                ldsm_x4(bf[2*j][0], bf[2*j][1], bf[2*j+1][0], bf[2*j+1][1],
                        s2u(&Bb[nrow * GST + ncol]));
            }
#pragma unroll
            for (int mt = 0; mt < 2; mt++)
#pragma unroll
                for (int nt = 0; nt < 8; nt++)
                    mma_f16(c[mt][nt], a[mt], bf[nt]);
        }
        __syncthreads();
    }

    // Epilogue
    int which = bn >> 10;       // MODE 1: 0=Q 1=K 2=V (uniform per CTA)
    int cc0   = bn & 1023;
    float scale = (MODE == 1 && which == 0) ? 0.125f : 1.0f;
#pragma unroll
    for (int mt = 0; mt < 2; mt++) {
        int r0 = bm + wm + mt * 16 + lm;
        int b  = r0 / S_;
        int s  = r0 - b * S_;
#pragma unroll
        for (int nt = 0; nt < 8; nt++) {
            int col = wn + nt * 8 + 2 * lk;
            if (MODE == 1) {
                int cc = cc0 + col;
                const float* bias = (which == 0) ? b0p : (which == 1) ? b1p : b2p;
                __half* C = (which == 0) ? (__half*)C0v
                          : (which == 1) ? (__half*)C1v : (__half*)C2v;
                float bv0 = bias[cc], bv1 = bias[cc + 1];
                float v00 = (c[mt][nt][0] + bv0) * scale;
                float v01 = (c[mt][nt][1] + bv1) * scale;
                float v10 = (c[mt][nt][2] + bv0) * scale;
                float v11 = (c[mt][nt][3] + bv1) * scale;
                int h  = cc >> 6;
                int hd = cc & 63;
                __half2* p0 = (__half2*)&C[(((size_t)(b * H_ + h)) * S_ + s    ) * HD_ + hd];
                __half2* p1 = (__half2*)&C[(((size_t)(b * H_ + h)) * S_ + s + 8) * HD_ + hd];
                *p0 = __floats2half2_rn(v00, v01);
                *p1 = __floats2half2_rn(v10, v11);
            } else {            // O-proj: fp32 transposed [B,D,S]
                int gcol = bn + col;
                float* C = (float*)C0v;
                float bv0 = b0p[gcol], bv1 = b0p[gcol + 1];
                C[((size_t)b * D_ + gcol    ) * S_ + s    ] = c[mt][nt][0] + bv0;
                C[((size_t)b * D_ + gcol + 1) * S_ + s    ] = c[mt][nt][1] + bv1;
                C[((size_t)b * D_ + gcol    ) * S_ + s + 8] = c[mt][nt][2] + bv0;
                C[((size_t)b * D_ + gcol + 1) * S_ + s + 8] = c[mt][nt][3] + bv1;
            }
        }
    }
}

// ---------------------------------------------------------------------------
// 4) Flash attention (unchanged from R10), fp16 mma + ldmatrix.
//    Grid (S/128, B*H), 256 thr.
// ---------------------------------------------------------------------------
#define AST 72
#define PST 72
#define ATTN_SMEM_BYTES ((128*AST + 2*64*AST + 2*64*AST + 8*16*PST) * 2)  // 73728

__global__ void __launch_bounds__(256, 2)
flash_attn() {
    extern __shared__ __half sh[];
    __half* Qs = sh;                       // [128][72]
    __half* Ks = Qs + 128 * AST;           // [2][64][72]   [key][d]
    __half* Vs = Ks + 2 * 64 * AST;        // [2][64][72]   [key][d]
    __half* Ps = Vs + 2 * 64 * AST;        // [8][16][72]   per-warp P

    int t = threadIdx.x, w = t >> 5, lane = t & 31;
    int lm = lane >> 2, lk = lane & 3;
    int bh = blockIdx.y;
    int qb = blockIdx.x * 128;
    size_t base = (size_t)bh * S_ * HD_;

    int rowg = t >> 3;   // 0..31
    int chk  = t & 7;    // 0..7
    int l15 = lane & 15;
    int lhi = (lane >> 4) * 8;

#pragma unroll
    for (int i = 0; i < 4; i++) {
        int r = rowg + i * 32;
        cpasync16(s2u(&Qs[r * AST + chk * 8]),
                  g_q + base + (size_t)(qb + r) * HD_ + chk * 8);
    }
    cp_commit();

    auto issue = [&](int kt, int p) {
#pragma unroll
        for (int i = 0; i < 2; i++) {
            int r = rowg + i * 32;
            cpasync16(s2u(&Ks[(p * 64 + r) * AST + chk * 8]),
                      g_k + base + (size_t)(kt + r) * HD_ + chk * 8);
            cpasync16(s2u(&Vs[(p * 64 + r) * AST + chk * 8]),
                      g_v + base + (size_t)(kt + r) * HD_ + chk * 8);
        }
        cp_commit();
    };

    issue(0, 0);

    float o[8][4];
#pragma unroll
    for (int nt = 0; nt < 8; nt++)
#pragma unroll
        for (int i = 0; i < 4; i++) o[nt][i] = 0.f;
    float m0 = -INFINITY, m1 = -INFINITY, l0 = 0.f, l1 = 0.f;

    __half* Pw = Ps + w * 16 * PST;

    const int NT = S_ / 64;
    for (int it = 0; it < NT; it++) {
        int p = it & 1;
        cp_wait0();
        __syncthreads();
        if (it + 1 < NT) issue((it + 1) * 64, 1 - p);

        const __half* Kb = Ks + p * 64 * AST;
        const __half* Vb = Vs + p * 64 * AST;

        // S = Q K^T
        float sacc[8][4];
#pragma unroll
        for (int nt = 0; nt < 8; nt++)
#pragma unroll
            for (int i = 0; i < 4; i++) sacc[nt][i] = 0.f;

#pragma unroll
        for (int ks = 0; ks < 4; ks++) {
            int kb = ks * 16;
            uint32_t a[4];
            ldsm_x4(a[0], a[1], a[2], a[3],
                    s2u(&Qs[(w * 16 + l15) * AST + kb + lhi]));
            uint32_t bf[8][2];
#pragma unroll
            for (int j = 0; j < 4; j++) {
                int g = lane >> 3;
                int nrow = (2 * j + (g >> 1)) * 8 + (lane & 7);
                int ncol = kb + (g & 1) * 8;
                ldsm_x4(bf[2*j][0], bf[2*j][1], bf[2*j+1][0], bf[2*j+1][1],
                        s2u(&Kb[nrow * AST + ncol]));
            }
#pragma unroll
            for (int nt = 0; nt < 8; nt++)
                mma_f16(sacc[nt], a, bf[nt]);
        }

        // Online softmax (rows lm, lm+8)
        float mx0 = -INFINITY, mx1 = -INFINITY;
#pragma unroll
        for (int nt = 0; nt < 8; nt++) {
            mx0 = fmaxf(mx0, fmaxf(sacc[nt][0], sacc[nt][1]));
            mx1 = fmaxf(mx1, fmaxf(sacc[nt][2], sacc[nt][3]));
        }
        mx0 = fmaxf(mx0, __shfl_xor_sync(0xffffffffu, mx0, 1));
        mx0 = fmaxf(mx0, __shfl_xor_sync(0xffffffffu, mx0, 2));
        mx1 = fmaxf(mx1, __shfl_xor_sync(0xffffffffu, mx1, 1));
        mx1 = fmaxf(mx1, __shfl_xor_sync(0xffffffffu, mx1, 2));

        float nm0 = fmaxf(m0, mx0), nm1 = fmaxf(m1, mx1);
        float sc0 = __expf(m0 - nm0), sc1 = __expf(m1 - nm1);
        float rs0 = 0.f, rs1 = 0.f;
#pragma unroll
        for (int nt = 0; nt < 8; nt++) {
            sacc[nt][0] = __expf(sacc[nt][0] - nm0);
            sacc[nt][1] = __expf(sacc[nt][1] - nm0);
            sacc[nt][2] = __expf(sacc[nt][2] - nm1);
            sacc[nt][3] = __expf(sacc[nt][3] - nm1);
            rs0 += sacc[nt][0] + sacc[nt][1];
            rs1 += sacc[nt][2] + sacc[nt][3];
        }
        rs0 += __shfl_xor_sync(0xffffffffu, rs0, 1);
        rs0 += __shfl_xor_sync(0xffffffffu, rs0, 2);
        rs1 += __shfl_xor_sync(0xffffffffu, rs1, 1);
        rs1 += __shfl_xor_sync(0xffffffffu, rs1, 2);

        l0 = l0 * sc0 + rs0;  l1 = l1 * sc1 + rs1;
        m0 = nm0;             m1 = nm1;
#pragma unroll
        for (int nt = 0; nt < 8; nt++) {
            o[nt][0] *= sc0; o[nt][1] *= sc0;
            o[nt][2] *= sc1; o[nt][3] *= sc1;
        }

        // P (C-frag) -> per-warp smem, packed STS.32 (conflict-free)
#pragma unroll
        for (int nt = 0; nt < 8; nt++) {
            int kc = nt * 8 + 2 * lk;
            *(uint32_t*)&Pw[(lm    ) * PST + kc] = packh2(sacc[nt][0], sacc[nt][1]);
            *(uint32_t*)&Pw[(lm + 8) * PST + kc] = packh2(sacc[nt][2], sacc[nt][3]);
        }
        __syncwarp();

        // O += P V   (A-frags: ldmatrix on Pw; B-frags: ldmatrix.trans on V)
#pragma unroll
        for (int ks = 0; ks < 4; ks++) {
            int kb = ks * 16;
            uint32_t a[4];
            ldsm_x4(a[0], a[1], a[2], a[3],
                    s2u(&Pw[l15 * PST + kb + lhi]));
#pragma unroll
            for (int j = 0; j < 4; j++) {
                uint32_t b0, b1, b2, b3;
                int vrow = kb + l15;
                int vcol = (2 * j) * 8 + lhi;
                ldsm_x4_t(b0, b1, b2, b3, s2u(&Vb[vrow * AST + vcol]));
                uint32_t bb0[2] = {b0, b1};
                uint32_t bb1[2] = {b2, b3};
                mma_f16(o[2*j    ], a, bb0);
                mma_f16(o[2*j + 1], a, bb1);
            }
        }
        __syncwarp();
    }

    // Epilogue: normalize, write ctx[B,S,D] fp16
    float inv0 = 1.f / l0, inv1 = 1.f / l1;
    int b = bh / H_, h = bh - b * H_;
    int srow = qb + w * 16 + lm;
#pragma unroll
    for (int nt = 0; nt < 8; nt++) {
        int col = h * HD_ + nt * 8 + 2 * lk;
        __half2* p0 = (__half2*)&g_ctx[((size_t)b * S_ + srow    ) * D_ + col];
        __half2* p1 = (__half2*)&g_ctx[((size_t)b * S_ + srow + 8) * D_ + col];
        *p0 = __floats2half2_rn(o[nt][0] * inv0, o[nt][1] * inv0);
        *p1 = __floats2half2_rn(o[nt][2] * inv1, o[nt][3] * inv1);
    }
}

// ---------------------------------------------------------------------------
// Launch
// ---------------------------------------------------------------------------
extern "C" void kernel_launch(void* const* d_in, const int* in_sizes, int n_in,
                              void* d_out, int out_size) {
    (void)in_sizes; (void)n_in; (void)out_size;
    const float* x  = (const float*)d_in[0];
    const float* Wq = (const float*)d_in[1];
    const float* bq = (const float*)d_in[2];
    const float* Wk = (const float*)d_in[3];
    const float* bk = (const float*)d_in[4];
    const float* Wv = (const float*)d_in[5];
    const float* bv = (const float*)d_in[6];
    const float* Wo = (const float*)d_in[7];
    const float* bo = (const float*)d_in[8];
    float* out = (float*)d_out;

    __half *xt, *q, *k, *v, *ctx, *wqkv, *wo;
    cudaGetSymbolAddress((void**)&xt,   g_xt);
    cudaGetSymbolAddress((void**)&q,    g_q);
    cudaGetSymbolAddress((void**)&k,    g_k);
    cudaGetSymbolAddress((void**)&v,    g_v);
    cudaGetSymbolAddress((void**)&ctx,  g_ctx);
    cudaGetSymbolAddress((void**)&wqkv, g_wqkv);
    cudaGetSymbolAddress((void**)&wo,   g_wo);

    cudaFuncSetAttribute(gemm_f16<1>, cudaFuncAttributeMaxDynamicSharedMemorySize,
                         GEMM_SMEM);
    cudaFuncSetAttribute(gemm_f16<2>, cudaFuncAttributeMaxDynamicSharedMemorySize,
                         GEMM_SMEM);
    cudaFuncSetAttribute(flash_attn, cudaFuncAttributeMaxDynamicSharedMemorySize,
                         ATTN_SMEM_BYTES);

    // 0) weights -> fp16 scratch
    weight_prep<<<(D_ * D_ / 4 + 255) / 256, 256>>>(Wq, Wk, Wv, Wo);
    // 1) PE table
    pe_kernel<<<(D_ * S_ + 255) / 256, 256>>>();
    // 2) x + PE -> xt[B,S,D] fp16
    addpe_transpose<<<dim3(S_ / 32, D_ / 32, B_), dim3(32, 8)>>>(x);
    // 3) fused QKV projection (N=3072) -> q,k,v all [BH][S][hd] fp16
    gemm_f16<1><<<dim3(3 * D_ / 128, BS_ / 128), 256, GEMM_SMEM>>>(
        xt, wqkv, bq, bk, bv, q, k, v, D_);
    // 4) attention -> ctx[B,S,D] fp16
    flash_attn<<<dim3(S_ / 128, B_ * H_), 256, ATTN_SMEM_BYTES>>>();
    // 5) output projection -> [B,D,S] fp32
    gemm_f16<2><<<dim3(D_ / 128, BS_ / 128), 256, GEMM_SMEM>>>(
        ctx, wo, bo, nullptr, nullptr, out, nullptr, nullptr, D_);
}

// round 13
// speedup vs baseline: 4.1777x; 1.3382x over previous
#include <cuda_runtime.h>
#include <cuda_fp16.h>
#include <cstdint>
#include <math.h>

// Problem constants
#define B_  4
#define D_  1024
#define S_  2048
#define H_  16
#define HD_ 64
#define BS_ (B_*S_)

// ---------------------------------------------------------------------------
// Scratch (static device globals — no allocation allowed)
// ---------------------------------------------------------------------------
__device__ float  g_pe  [D_*S_];             // positional encoding [D][S]
__device__ __half g_xt  [BS_*(size_t)D_];    // x+PE, [B,S,D]  fp16
__device__ __half g_q   [BS_*(size_t)D_];    // Q/8  [BH][S][hd] fp16
__device__ __half g_k   [BS_*(size_t)D_];    // K    [BH][S][hd] fp16
__device__ __half g_v   [BS_*(size_t)D_];    // V    [BH][S][hd] fp16
__device__ __half g_ctx [BS_*(size_t)D_];    // attention out [B,S,D] fp16
__device__ __half g_wqkv[3*D_*(size_t)D_];   // Wq|Wk|Wv stacked [3072][1024] fp16
__device__ __half g_wo  [D_*(size_t)D_];     // Wo fp16

// ---------------------------------------------------------------------------
// Helpers
// ---------------------------------------------------------------------------
__device__ __forceinline__ uint32_t s2u(const void* p) {
    return (uint32_t)__cvta_generic_to_shared(p);
}
__device__ __forceinline__ void cpasync16(uint32_t dst, const void* src) {
    asm volatile("cp.async.ca.shared.global [%0], [%1], 16;\n" :: "r"(dst), "l"(src));
}
__device__ __forceinline__ void cp_commit() {
    asm volatile("cp.async.commit_group;\n");
}
__device__ __forceinline__ void cp_wait0() {
    asm volatile("cp.async.wait_group 0;\n");
}
__device__ __forceinline__ void cp_wait1() {
    asm volatile("cp.async.wait_group 1;\n");
}

// fp16 mma: m16n8k16, fp32 accumulate
__device__ __forceinline__ void mma_f16(float* c, const uint32_t* a, const uint32_t* b) {
    asm volatile(
        "mma.sync.aligned.m16n8k16.row.col.f32.f16.f16.f32 "
        "{%0,%1,%2,%3}, {%4,%5,%6,%7}, {%8,%9}, {%0,%1,%2,%3};\n"
        : "+f"(c[0]), "+f"(c[1]), "+f"(c[2]), "+f"(c[3])
        : "r"(a[0]), "r"(a[1]), "r"(a[2]), "r"(a[3]), "r"(b[0]), "r"(b[1]));
}

__device__ __forceinline__ void ldsm_x4(uint32_t& r0, uint32_t& r1, uint32_t& r2,
                                        uint32_t& r3, uint32_t addr) {
    asm volatile("ldmatrix.sync.aligned.m8n8.x4.shared.b16 {%0,%1,%2,%3}, [%4];"
                 : "=r"(r0), "=r"(r1), "=r"(r2), "=r"(r3) : "r"(addr));
}
__device__ __forceinline__ void ldsm_x4_t(uint32_t& r0, uint32_t& r1, uint32_t& r2,
                                          uint32_t& r3, uint32_t addr) {
    asm volatile("ldmatrix.sync.aligned.m8n8.x4.trans.shared.b16 {%0,%1,%2,%3}, [%4];"
                 : "=r"(r0), "=r"(r1), "=r"(r2), "=r"(r3) : "r"(addr));
}

// pack two f32 exponents to f16x2 (lo = x, hi = y), then exp2 in f16x2
__device__ __forceinline__ uint32_t exp2_f16x2(float x, float y) {
    uint32_t p;
    asm("cvt.rn.f16x2.f32 %0, %1, %2;" : "=r"(p) : "f"(y), "f"(x));
    asm("ex2.approx.f16x2 %0, %1;" : "=r"(p) : "r"(p));
    return p;
}

// ---------------------------------------------------------------------------
// 0) Weight prep: convert weights to fp16 (Wq|Wk|Wv stacked, Wo)
// ---------------------------------------------------------------------------
__global__ void weight_prep(const float* __restrict__ Wq, const float* __restrict__ Wk,
                            const float* __restrict__ Wv, const float* __restrict__ Wo) {
    int idx4 = blockIdx.x * blockDim.x + threadIdx.x;
    const int NW = D_ * D_ / 4;
    if (idx4 >= NW) return;
    float4 a = ((const float4*)Wq)[idx4];
    float4 b = ((const float4*)Wk)[idx4];
    float4 c = ((const float4*)Wv)[idx4];
    float4 d = ((const float4*)Wo)[idx4];
    __half2* wq2 = (__half2*)g_wqkv;
    __half2* wo2 = (__half2*)g_wo;
    wq2[2*idx4    ]        = __floats2half2_rn(a.x, a.y);
    wq2[2*idx4 + 1]        = __floats2half2_rn(a.z, a.w);
    wq2[2*(idx4+NW)    ]   = __floats2half2_rn(b.x, b.y);
    wq2[2*(idx4+NW) + 1]   = __floats2half2_rn(b.z, b.w);
    wq2[2*(idx4+2*NW)    ] = __floats2half2_rn(c.x, c.y);
    wq2[2*(idx4+2*NW) + 1] = __floats2half2_rn(c.z, c.w);
    wo2[2*idx4    ]        = __floats2half2_rn(d.x, d.y);
    wo2[2*idx4 + 1]        = __floats2half2_rn(d.z, d.w);
}

// ---------------------------------------------------------------------------
// 1) Positional encoding table — fp32 trig (abs err <=~1e-6; PE only perturbs
//    the O(1) input additively, so this is far below the error budget)
// ---------------------------------------------------------------------------
__global__ void pe_kernel() {
    int idx = blockIdx.x * blockDim.x + threadIdx.x;
    if (idx >= D_ * S_) return;
    int d = idx / S_;
    int s = idx - d * S_;
    float freq = expf((float)(d & ~1) * (-0.008994473019508f)); // -ln(1e4)/1024
    float ang  = (float)s * freq;
    g_pe[idx] = (d & 1) ? cosf(ang) : sinf(ang);
}

// ---------------------------------------------------------------------------
// 2) x[B,D,S] + pe[D,S]  ->  xt[B,S,D]  fp16
// ---------------------------------------------------------------------------
__global__ void addpe_transpose(const float* __restrict__ x) {
    __shared__ float tile[32][33];
    int b  = blockIdx.z;
    int d0 = blockIdx.y * 32;
    int s0 = blockIdx.x * 32;
    int tx = threadIdx.x, ty = threadIdx.y;  // (32, 8)
#pragma unroll
    for (int j = 0; j < 4; j++) {
        int d = d0 + ty + j * 8;
        tile[ty + j * 8][tx] = x[((size_t)b * D_ + d) * S_ + s0 + tx]
                             + g_pe[(size_t)d * S_ + s0 + tx];
    }
    __syncthreads();
#pragma unroll
    for (int j = 0; j < 4; j++) {
        int s = s0 + ty + j * 8;
        g_xt[((size_t)b * S_ + s) * D_ + d0 + tx] =
            __float2half_rn(tile[tx][ty + j * 8]);
    }
}

// ---------------------------------------------------------------------------
// 3/5) fp16 GEMM (unchanged from R11): CTA 128x128, warp 32x64, ldmatrix,
//      3-stage cp.async pipeline.
// ---------------------------------------------------------------------------
#define GST 40   // halves per smem row
#define GEMM_SMEM (3 * 2 * 128 * GST * 2)   // 61440 B

template <int MODE>
__global__ void __launch_bounds__(256, 2)
gemm_f16(const __half* __restrict__ A, const __half* __restrict__ W,
         const float* __restrict__ b0p, const float* __restrict__ b1p,
         const float* __restrict__ b2p,
         void* __restrict__ C0v, void* __restrict__ C1v, void* __restrict__ C2v,
         int K) {
    extern __shared__ __half gsm[];
    __half* As = gsm;                       // [3][128][GST]
    __half* Bs = gsm + 3 * 128 * GST;       // [3][128][GST]

    int t    = threadIdx.x;
    int wid  = t >> 5, lane = t & 31;
    int lm   = lane >> 2, lk = lane & 3;
    int wm   = (wid >> 1) * 32;
    int wn   = (wid & 1) * 64;
    int bm   = blockIdx.y * 128;
    int bn   = blockIdx.x * 128;
    int l15  = lane & 15;
    int lhi  = (lane >> 4) * 8;

    float c[2][8][4];
#pragma unroll
    for (int mt = 0; mt < 2; mt++)
#pragma unroll
        for (int nt = 0; nt < 8; nt++)
#pragma unroll
            for (int i = 0; i < 4; i++) c[mt][nt][i] = 0.f;

    int rowg = t >> 2;        // 0..63
    int chk  = t & 3;         // 0..3

    auto issue = [&](int k0, int st) {
#pragma unroll
        for (int i = 0; i < 2; i++) {
            int r = rowg + i * 64;
            cpasync16(s2u(&As[(st * 128 + r) * GST + chk * 8]),
                      A + (size_t)(bm + r) * K + k0 + chk * 8);
            cpasync16(s2u(&Bs[(st * 128 + r) * GST + chk * 8]),
                      W + (size_t)(bn + r) * K + k0 + chk * 8);
        }
        cp_commit();
    };

    int NT = K >> 5;          // 32
    issue(0, 0);
    issue(32, 1);

    for (int it = 0; it < NT; it++) {
        int st = it % 3;
        if (it == NT - 1) cp_wait0(); else cp_wait1();
        __syncthreads();
        if (it + 2 < NT) issue((it + 2) << 5, (it + 2) % 3);

        const __half* Ab = As + st * 128 * GST;
        const __half* Bb = Bs + st * 128 * GST;
#pragma unroll
        for (int ks = 0; ks < 2; ks++) {
            int kb = ks * 16;
            uint32_t a[2][4];
#pragma unroll
            for (int mt = 0; mt < 2; mt++)
                ldsm_x4(a[mt][0], a[mt][1], a[mt][2], a[mt][3],
                        s2u(&Ab[(wm + mt * 16 + l15) * GST + kb + lhi]));
            uint32_t bf[8][2];
#pragma unroll
            for (int j = 0; j < 4; j++) {
                int g = lane >> 3;
                int nrow = wn + (2 * j + (g >> 1)) * 8 + (lane & 7);
                int ncol = kb + (g & 1) * 8;
                ldsm_x4(bf[2*j][0], bf[2*j][1], bf[2*j+1][0], bf[2*j+1][1],
                        s2u(&Bb[nrow * GST + ncol]));
            }
#pragma unroll
            for (int mt = 0; mt < 2; mt++)
#pragma unroll
                for (int nt = 0; nt < 8; nt++)
                    mma_f16(c[mt][nt], a[mt], bf[nt]);
        }
        __syncthreads();
    }

    // Epilogue
    int which = bn >> 10;
    int cc0   = bn & 1023;
    float scale = (MODE == 1 && which == 0) ? 0.125f : 1.0f;
#pragma unroll
    for (int mt = 0; mt < 2; mt++) {
        int r0 = bm + wm + mt * 16 + lm;
        int b  = r0 / S_;
        int s  = r0 - b * S_;
#pragma unroll
        for (int nt = 0; nt < 8; nt++) {
            int col = wn + nt * 8 + 2 * lk;
            if (MODE == 1) {
                int cc = cc0 + col;
                const float* bias = (which == 0) ? b0p : (which == 1) ? b1p : b2p;
                __half* C = (which == 0) ? (__half*)C0v
                          : (which == 1) ? (__half*)C1v : (__half*)C2v;
                float bv0 = bias[cc], bv1 = bias[cc + 1];
                float v00 = (c[mt][nt][0] + bv0) * scale;
                float v01 = (c[mt][nt][1] + bv1) * scale;
                float v10 = (c[mt][nt][2] + bv0) * scale;
                float v11 = (c[mt][nt][3] + bv1) * scale;
                int h  = cc >> 6;
                int hd = cc & 63;
                __half2* p0 = (__half2*)&C[(((size_t)(b * H_ + h)) * S_ + s    ) * HD_ + hd];
                __half2* p1 = (__half2*)&C[(((size_t)(b * H_ + h)) * S_ + s + 8) * HD_ + hd];
                *p0 = __floats2half2_rn(v00, v01);
                *p1 = __floats2half2_rn(v10, v11);
            } else {            // O-proj: fp32 transposed [B,D,S]
                int gcol = bn + col;
                float* C = (float*)C0v;
                float bv0 = b0p[gcol], bv1 = b0p[gcol + 1];
                C[((size_t)b * D_ + gcol    ) * S_ + s    ] = c[mt][nt][0] + bv0;
                C[((size_t)b * D_ + gcol + 1) * S_ + s    ] = c[mt][nt][1] + bv1;
                C[((size_t)b * D_ + gcol    ) * S_ + s + 8] = c[mt][nt][2] + bv0;
                C[((size_t)b * D_ + gcol + 1) * S_ + s + 8] = c[mt][nt][3] + bv1;
            }
        }
    }
}

// ---------------------------------------------------------------------------
// 4) Flash attention.  Softmax via ex2.approx.f16x2 (half the MUFU ops,
//    produces P pre-packed for the STS); row-sums via a ones-B mma on the
//    tensor pipe (exact fp32 sum of the fp16 P actually used by PV — no
//    shuffle/add reduction at all).
// ---------------------------------------------------------------------------
#define AST 72
#define PST 72
#define ATTN_SMEM_BYTES ((128*AST + 2*64*AST + 2*64*AST + 8*16*PST) * 2)  // 73728

__global__ void __launch_bounds__(256, 2)
flash_attn() {
    extern __shared__ __half sh[];
    __half* Qs = sh;                       // [128][72]
    __half* Ks = Qs + 128 * AST;           // [2][64][72]   [key][d]
    __half* Vs = Ks + 2 * 64 * AST;        // [2][64][72]   [key][d]
    __half* Ps = Vs + 2 * 64 * AST;        // [8][16][72]   per-warp P

    int t = threadIdx.x, w = t >> 5, lane = t & 31;
    int lm = lane >> 2, lk = lane & 3;
    int bh = blockIdx.y;
    int qb = blockIdx.x * 128;
    size_t base = (size_t)bh * S_ * HD_;

    int rowg = t >> 3;   // 0..31
    int chk  = t & 7;    // 0..7
    int l15 = lane & 15;
    int lhi = (lane >> 4) * 8;
    const float L2E = 1.4426950408889634f;
    const uint32_t ONES2 = 0x3C003C00u;          // half2(1,1)
    uint32_t onesb[2] = {ONES2, ONES2};

#pragma unroll
    for (int i = 0; i < 4; i++) {
        int r = rowg + i * 32;
        cpasync16(s2u(&Qs[r * AST + chk * 8]),
                  g_q + base + (size_t)(qb + r) * HD_ + chk * 8);
    }
    cp_commit();

    auto issue = [&](int kt, int p) {
#pragma unroll
        for (int i = 0; i < 2; i++) {
            int r = rowg + i * 32;
            cpasync16(s2u(&Ks[(p * 64 + r) * AST + chk * 8]),
                      g_k + base + (size_t)(kt + r) * HD_ + chk * 8);
            cpasync16(s2u(&Vs[(p * 64 + r) * AST + chk * 8]),
                      g_v + base + (size_t)(kt + r) * HD_ + chk * 8);
        }
        cp_commit();
    };

    issue(0, 0);

    float o[8][4];
#pragma unroll
    for (int nt = 0; nt < 8; nt++)
#pragma unroll
        for (int i = 0; i < 4; i++) o[nt][i] = 0.f;
    float m0 = -INFINITY, m1 = -INFINITY, l0 = 0.f, l1 = 0.f;

    __half* Pw = Ps + w * 16 * PST;

    const int NT = S_ / 64;
    for (int it = 0; it < NT; it++) {
        int p = it & 1;
        cp_wait0();
        __syncthreads();
        if (it + 1 < NT) issue((it + 1) * 64, 1 - p);

        const __half* Kb = Ks + p * 64 * AST;
        const __half* Vb = Vs + p * 64 * AST;

        // S = Q K^T
        float sacc[8][4];
#pragma unroll
        for (int nt = 0; nt < 8; nt++)
#pragma unroll
            for (int i = 0; i < 4; i++) sacc[nt][i] = 0.f;

#pragma unroll
        for (int ks = 0; ks < 4; ks++) {
            int kb = ks * 16;
            uint32_t a[4];
            ldsm_x4(a[0], a[1], a[2], a[3],
                    s2u(&Qs[(w * 16 + l15) * AST + kb + lhi]));
            uint32_t bf[8][2];
#pragma unroll
            for (int j = 0; j < 4; j++) {
                int g = lane >> 3;
                int nrow = (2 * j + (g >> 1)) * 8 + (lane & 7);
                int ncol = kb + (g & 1) * 8;
                ldsm_x4(bf[2*j][0], bf[2*j][1], bf[2*j+1][0], bf[2*j+1][1],
                        s2u(&Kb[nrow * AST + ncol]));
            }
#pragma unroll
            for (int nt = 0; nt < 8; nt++)
                mma_f16(sacc[nt], a, bf[nt]);
        }

        // Row max (rows lm, lm+8; 4 lanes per row -> xor 1,2)
        float mx0 = -INFINITY, mx1 = -INFINITY;
#pragma unroll
        for (int nt = 0; nt < 8; nt++) {
            mx0 = fmaxf(mx0, fmaxf(sacc[nt][0], sacc[nt][1]));
            mx1 = fmaxf(mx1, fmaxf(sacc[nt][2], sacc[nt][3]));
        }
        mx0 = fmaxf(mx0, __shfl_xor_sync(0xffffffffu, mx0, 1));
        mx0 = fmaxf(mx0, __shfl_xor_sync(0xffffffffu, mx0, 2));
        mx1 = fmaxf(mx1, __shfl_xor_sync(0xffffffffu, mx1, 1));
        mx1 = fmaxf(mx1, __shfl_xor_sync(0xffffffffu, mx1, 2));

        float nm0 = fmaxf(m0, mx0), nm1 = fmaxf(m1, mx1);
        float sc0 = __expf(m0 - nm0), sc1 = __expf(m1 - nm1);
        float bb0 = nm0 * L2E, bb1 = nm1 * L2E;
        m0 = nm0;  m1 = nm1;

        // P = exp2((s-m)*log2e) in f16x2, stored straight to Pw
#pragma unroll
        for (int nt = 0; nt < 8; nt++) {
            float e00 = fmaf(sacc[nt][0], L2E, -bb0);
            float e01 = fmaf(sacc[nt][1], L2E, -bb0);
            float e10 = fmaf(sacc[nt][2], L2E, -bb1);
            float e11 = fmaf(sacc[nt][3], L2E, -bb1);
            int kc = nt * 8 + 2 * lk;
            *(uint32_t*)&Pw[(lm    ) * PST + kc] = exp2_f16x2(e00, e01);
            *(uint32_t*)&Pw[(lm + 8) * PST + kc] = exp2_f16x2(e10, e11);
        }

#pragma unroll
        for (int nt = 0; nt < 8; nt++) {
            o[nt][0] *= sc0; o[nt][1] *= sc0;
            o[nt][2] *= sc1; o[nt][3] *= sc1;
        }
        __syncwarp();

        // O += P V ; row-sum of P via ones-B mma (tensor pipe, exact fp32)
        float lacc[4] = {0.f, 0.f, 0.f, 0.f};
#pragma unroll
        for (int ks = 0; ks < 4; ks++) {
            int kb = ks * 16;
            uint32_t a[4];
            ldsm_x4(a[0], a[1], a[2], a[3],
                    s2u(&Pw[l15 * PST + kb + lhi]));
            mma_f16(lacc, a, onesb);
#pragma unroll
            for (int j = 0; j < 4; j++) {
                uint32_t b0, b1, b2, b3;
                int vrow = kb + l15;
                int vcol = (2 * j) * 8 + lhi;
                ldsm_x4_t(b0, b1, b2, b3, s2u(&Vb[vrow * AST + vcol]));
                uint32_t bb0v[2] = {b0, b1};
                uint32_t bb1v[2] = {b2, b3};
                mma_f16(o[2*j    ], a, bb0v);
                mma_f16(o[2*j + 1], a, bb1v);
            }
        }
        l0 = l0 * sc0 + lacc[0];
        l1 = l1 * sc1 + lacc[2];
        __syncwarp();
    }

    // Epilogue: normalize, write ctx[B,S,D] fp16
    float inv0 = 1.f / l0, inv1 = 1.f / l1;
    int b = bh / H_, h = bh - b * H_;
    int srow = qb + w * 16 + lm;
#pragma unroll
    for (int nt = 0; nt < 8; nt++) {
        int col = h * HD_ + nt * 8 + 2 * lk;
        __half2* p0 = (__half2*)&g_ctx[((size_t)b * S_ + srow    ) * D_ + col];
        __half2* p1 = (__half2*)&g_ctx[((size_t)b * S_ + srow + 8) * D_ + col];
        *p0 = __floats2half2_rn(o[nt][0] * inv0, o[nt][1] * inv0);
        *p1 = __floats2half2_rn(o[nt][2] * inv1, o[nt][3] * inv1);
    }
}

// ---------------------------------------------------------------------------
// Launch
// ---------------------------------------------------------------------------
extern "C" void kernel_launch(void* const* d_in, const int* in_sizes, int n_in,
                              void* d_out, int out_size) {
    (void)in_sizes; (void)n_in; (void)out_size;
    const float* x  = (const float*)d_in[0];
    const float* Wq = (const float*)d_in[1];
    const float* bq = (const float*)d_in[2];
    const float* Wk = (const float*)d_in[3];
    const float* bk = (const float*)d_in[4];
    const float* Wv = (const float*)d_in[5];
    const float* bv = (const float*)d_in[6];
    const float* Wo = (const float*)d_in[7];
    const float* bo = (const float*)d_in[8];
    float* out = (float*)d_out;

    __half *xt, *q, *k, *v, *ctx, *wqkv, *wo;
    cudaGetSymbolAddress((void**)&xt,   g_xt);
    cudaGetSymbolAddress((void**)&q,    g_q);
    cudaGetSymbolAddress((void**)&k,    g_k);
    cudaGetSymbolAddress((void**)&v,    g_v);
    cudaGetSymbolAddress((void**)&ctx,  g_ctx);
    cudaGetSymbolAddress((void**)&wqkv, g_wqkv);
    cudaGetSymbolAddress((void**)&wo,   g_wo);

    cudaFuncSetAttribute(gemm_f16<1>, cudaFuncAttributeMaxDynamicSharedMemorySize,
                         GEMM_SMEM);
    cudaFuncSetAttribute(gemm_f16<2>, cudaFuncAttributeMaxDynamicSharedMemorySize,
                         GEMM_SMEM);
    cudaFuncSetAttribute(flash_attn, cudaFuncAttributeMaxDynamicSharedMemorySize,
                         ATTN_SMEM_BYTES);

    // 0) weights -> fp16 scratch
    weight_prep<<<(D_ * D_ / 4 + 255) / 256, 256>>>(Wq, Wk, Wv, Wo);
    // 1) PE table (fp32)
    pe_kernel<<<(D_ * S_ + 255) / 256, 256>>>();
    // 2) x + PE -> xt[B,S,D] fp16
    addpe_transpose<<<dim3(S_ / 32, D_ / 32, B_), dim3(32, 8)>>>(x);
    // 3) fused QKV projection (N=3072) -> q,k,v all [BH][S][hd] fp16
    gemm_f16<1><<<dim3(3 * D_ / 128, BS_ / 128), 256, GEMM_SMEM>>>(
        xt, wqkv, bq, bk, bv, q, k, v, D_);
    // 4) attention -> ctx[B,S,D] fp16
    flash_attn<<<dim3(S_ / 128, B_ * H_), 256, ATTN_SMEM_BYTES>>>();
    // 5) output projection -> [B,D,S] fp32
    gemm_f16<2><<<dim3(D_ / 128, BS_ / 128), 256, GEMM_SMEM>>>(
        ctx, wo, bo, nullptr, nullptr, out, nullptr, nullptr, D_);
}

// round 16
// speedup vs baseline: 4.5828x; 1.0970x over previous
#include <cuda_runtime.h>
#include <cuda_fp16.h>
#include <cstdint>
#include <math.h>

// Problem constants
#define B_  4
#define D_  1024
#define S_  2048
#define H_  16
#define HD_ 64
#define BS_ (B_*S_)

// ---------------------------------------------------------------------------
// Scratch (static device globals — no allocation allowed)
// ---------------------------------------------------------------------------
__device__ __half g_xt  [BS_*(size_t)D_];    // x+PE, [B,S,D]  fp16
__device__ __half g_q   [BS_*(size_t)D_];    // Q/8  [BH][S][hd] fp16
__device__ __half g_k   [BS_*(size_t)D_];    // K    [BH][S][hd] fp16
__device__ __half g_v   [BS_*(size_t)D_];    // V    [BH][S][hd] fp16
__device__ __half g_ctx [BS_*(size_t)D_];    // attention out [B,S,D] fp16
__device__ __half g_wqkv[3*D_*(size_t)D_];   // Wq|Wk|Wv stacked [3072][1024] fp16
__device__ __half g_wo  [D_*(size_t)D_];     // Wo fp16

// ---------------------------------------------------------------------------
// Helpers
// ---------------------------------------------------------------------------
__device__ __forceinline__ uint32_t s2u(const void* p) {
    return (uint32_t)__cvta_generic_to_shared(p);
}
__device__ __forceinline__ void cpasync16(uint32_t dst, const void* src) {
    asm volatile("cp.async.cg.shared.global [%0], [%1], 16;\n" :: "r"(dst), "l"(src));
}
__device__ __forceinline__ void cp_commit() {
    asm volatile("cp.async.commit_group;\n");
}
__device__ __forceinline__ void cp_wait0() {
    asm volatile("cp.async.wait_group 0;\n");
}
__device__ __forceinline__ void cp_wait1() {
    asm volatile("cp.async.wait_group 1;\n");
}

// fp16 mma: m16n8k16, fp32 accumulate
__device__ __forceinline__ void mma_f16(float* c, const uint32_t* a, const uint32_t* b) {
    asm volatile(
        "mma.sync.aligned.m16n8k16.row.col.f32.f16.f16.f32 "
        "{%0,%1,%2,%3}, {%4,%5,%6,%7}, {%8,%9}, {%0,%1,%2,%3};\n"
        : "+f"(c[0]), "+f"(c[1]), "+f"(c[2]), "+f"(c[3])
        : "r"(a[0]), "r"(a[1]), "r"(a[2]), "r"(a[3]), "r"(b[0]), "r"(b[1]));
}

__device__ __forceinline__ void ldsm_x4(uint32_t& r0, uint32_t& r1, uint32_t& r2,
                                        uint32_t& r3, uint32_t addr) {
    asm volatile("ldmatrix.sync.aligned.m8n8.x4.shared.b16 {%0,%1,%2,%3}, [%4];"
                 : "=r"(r0), "=r"(r1), "=r"(r2), "=r"(r3) : "r"(addr));
}
__device__ __forceinline__ void ldsm_x4_t(uint32_t& r0, uint32_t& r1, uint32_t& r2,
                                          uint32_t& r3, uint32_t addr) {
    asm volatile("ldmatrix.sync.aligned.m8n8.x4.trans.shared.b16 {%0,%1,%2,%3}, [%4];"
                 : "=r"(r0), "=r"(r1), "=r"(r2), "=r"(r3) : "r"(addr));
}

// pack two f32 exponents to f16x2 (lo = x, hi = y), then exp2 in f16x2
__device__ __forceinline__ uint32_t exp2_f16x2(float x, float y) {
    uint32_t p;
    asm("cvt.rn.f16x2.f32 %0, %1, %2;" : "=r"(p) : "f"(y), "f"(x));
    asm("ex2.approx.f16x2 %0, %1;" : "=r"(p) : "r"(p));
    return p;
}

// ---------------------------------------------------------------------------
// 0) Weight prep: convert weights to fp16 (Wq|Wk|Wv stacked, Wo)
// ---------------------------------------------------------------------------
__global__ void weight_prep(const float* __restrict__ Wq, const float* __restrict__ Wk,
                            const float* __restrict__ Wv, const float* __restrict__ Wo) {
    int idx4 = blockIdx.x * blockDim.x + threadIdx.x;
    const int NW = D_ * D_ / 4;
    if (idx4 >= NW) return;
    float4 a = ((const float4*)Wq)[idx4];
    float4 b = ((const float4*)Wk)[idx4];
    float4 c = ((const float4*)Wv)[idx4];
    float4 d = ((const float4*)Wo)[idx4];
    __half2* wq2 = (__half2*)g_wqkv;
    __half2* wo2 = (__half2*)g_wo;
    wq2[2*idx4    ]        = __floats2half2_rn(a.x, a.y);
    wq2[2*idx4 + 1]        = __floats2half2_rn(a.z, a.w);
    wq2[2*(idx4+NW)    ]   = __floats2half2_rn(b.x, b.y);
    wq2[2*(idx4+NW) + 1]   = __floats2half2_rn(b.z, b.w);
    wq2[2*(idx4+2*NW)    ] = __floats2half2_rn(c.x, c.y);
    wq2[2*(idx4+2*NW) + 1] = __floats2half2_rn(c.z, c.w);
    wo2[2*idx4    ]        = __floats2half2_rn(d.x, d.y);
    wo2[2*idx4 + 1]        = __floats2half2_rn(d.z, d.w);
}

// ---------------------------------------------------------------------------
// 1+2) x[B,D,S] + PE(d,s)  ->  xt[B,S,D] fp16   (PE computed inline, fp32
//      trig — same formula as before, just no global round-trip)
// ---------------------------------------------------------------------------
__global__ void addpe_transpose(const float* __restrict__ x) {
    __shared__ float tile[32][33];
    int b  = blockIdx.z;
    int d0 = blockIdx.y * 32;
    int s0 = blockIdx.x * 32;
    int tx = threadIdx.x, ty = threadIdx.y;  // (32, 8)
#pragma unroll
    for (int j = 0; j < 4; j++) {
        int d = d0 + ty + j * 8;
        float freq = expf((float)(d & ~1) * (-0.008994473019508f)); // -ln(1e4)/1024
        float ang  = (float)(s0 + tx) * freq;
        float pe   = (d & 1) ? cosf(ang) : sinf(ang);
        tile[ty + j * 8][tx] = x[((size_t)b * D_ + d) * S_ + s0 + tx] + pe;
    }
    __syncthreads();
#pragma unroll
    for (int j = 0; j < 4; j++) {
        int s = s0 + ty + j * 8;
        g_xt[((size_t)b * S_ + s) * D_ + d0 + tx] =
            __float2half_rn(tile[tx][ty + j * 8]);
    }
}

// ---------------------------------------------------------------------------
// 3/5) fp16 GEMM:  C[M,N] = A[M,K] @ W[N,K]^T + bias.
//      CTA 128x128, BK=64 (half the barrier cadence of BK=32), 256 thr,
//      warp tile 32x64, ldmatrix fragments, 2-stage cp.async pipeline (.cg).
// MODE 1: fused QKV (N=3072): Q scaled 1/8; Q/K/V all -> [BH][S][hd] fp16.
// MODE 2: O-proj: output fp32 transposed to [B,D,S].
// ---------------------------------------------------------------------------
#define GST 72   // halves per smem row (64 + 8 pad); 144B stride, ldsm-clean
#define GEMM_SMEM (2 * 2 * 128 * GST * 2)   // 73728 B

template <int MODE>
__global__ void __launch_bounds__(256, 2)
gemm_f16(const __half* __restrict__ A, const __half* __restrict__ W,
         const float* __restrict__ b0p, const float* __restrict__ b1p,
         const float* __restrict__ b2p,
         void* __restrict__ C0v, void* __restrict__ C1v, void* __restrict__ C2v,
         int K) {
    extern __shared__ __half gsm[];
    __half* As = gsm;                       // [2][128][GST]
    __half* Bs = gsm + 2 * 128 * GST;       // [2][128][GST]

    int t    = threadIdx.x;
    int wid  = t >> 5, lane = t & 31;
    int lm   = lane >> 2, lk = lane & 3;
    int wm   = (wid >> 1) * 32;
    int wn   = (wid & 1) * 64;
    int bm   = blockIdx.y * 128;
    int bn   = blockIdx.x * 128;
    int l15  = lane & 15;
    int lhi  = (lane >> 4) * 8;

    float c[2][8][4];
#pragma unroll
    for (int mt = 0; mt < 2; mt++)
#pragma unroll
        for (int nt = 0; nt < 8; nt++)
#pragma unroll
            for (int i = 0; i < 4; i++) c[mt][nt][i] = 0.f;

    // 128 rows x 8 chunks(16B) per tile = 1024 chunks; 4 per thread (A and B)
    auto issue = [&](int k0, int st) {
#pragma unroll
        for (int i = 0; i < 4; i++) {
            int ci = t + i * 256;
            int r = ci >> 3, ch = ci & 7;
            cpasync16(s2u(&As[(st * 128 + r) * GST + ch * 8]),
                      A + (size_t)(bm + r) * K + k0 + ch * 8);
        }
#pragma unroll
        for (int i = 0; i < 4; i++) {
            int ci = t + i * 256;
            int r = ci >> 3, ch = ci & 7;
            cpasync16(s2u(&Bs[(st * 128 + r) * GST + ch * 8]),
                      W + (size_t)(bn + r) * K + k0 + ch * 8);
        }
        cp_commit();
    };

    int NT = K >> 6;          // 16
    issue(0, 0);
    issue(64, 1);

    for (int it = 0; it < NT; it++) {
        int st = it & 1;
        if (it >= NT - 1) cp_wait0(); else cp_wait1();
        __syncthreads();

        const __half* Ab = As + st * 128 * GST;
        const __half* Bb = Bs + st * 128 * GST;
#pragma unroll
        for (int ks = 0; ks < 4; ks++) {
            int kb = ks * 16;
            uint32_t a[2][4];
#pragma unroll
            for (int mt = 0; mt < 2; mt++)
                ldsm_x4(a[mt][0], a[mt][1], a[mt][2], a[mt][3],
                        s2u(&Ab[(wm + mt * 16 + l15) * GST + kb + lhi]));
            uint32_t bf[8][2];
#pragma unroll
            for (int j = 0; j < 4; j++) {
                int g = lane >> 3;
                int nrow = wn + (2 * j + (g >> 1)) * 8 + (lane & 7);
                int ncol = kb + (g & 1) * 8;
                ldsm_x4(bf[2*j][0], bf[2*j][1], bf[2*j+1][0], bf[2*j+1][1],
                        s2u(&Bb[nrow * GST + ncol]));
            }
#pragma unroll
            for (int mt = 0; mt < 2; mt++)
#pragma unroll
                for (int nt = 0; nt < 8; nt++)
                    mma_f16(c[mt][nt], a[mt], bf[nt]);
        }
        __syncthreads();
        if (it + 2 < NT) issue((it + 2) << 6, st);
    }

    // Epilogue
    int which = bn >> 10;
    int cc0   = bn & 1023;
    float scale = (MODE == 1 && which == 0) ? 0.125f : 1.0f;
#pragma unroll
    for (int mt = 0; mt < 2; mt++) {
        int r0 = bm + wm + mt * 16 + lm;
        int b  = r0 / S_;
        int s  = r0 - b * S_;
#pragma unroll
        for (int nt = 0; nt < 8; nt++) {
            int col = wn + nt * 8 + 2 * lk;
            if (MODE == 1) {
                int cc = cc0 + col;
                const float* bias = (which == 0) ? b0p : (which == 1) ? b1p : b2p;
                __half* C = (which == 0) ? (__half*)C0v
                          : (which == 1) ? (__half*)C1v : (__half*)C2v;
                float bv0 = bias[cc], bv1 = bias[cc + 1];
                float v00 = (c[mt][nt][0] + bv0) * scale;
                float v01 = (c[mt][nt][1] + bv1) * scale;
                float v10 = (c[mt][nt][2] + bv0) * scale;
                float v11 = (c[mt][nt][3] + bv1) * scale;
                int h  = cc >> 6;
                int hd = cc & 63;
                __half2* p0 = (__half2*)&C[(((size_t)(b * H_ + h)) * S_ + s    ) * HD_ + hd];
                __half2* p1 = (__half2*)&C[(((size_t)(b * H_ + h)) * S_ + s + 8) * HD_ + hd];
                *p0 = __floats2half2_rn(v00, v01);
                *p1 = __floats2half2_rn(v10, v11);
            } else {            // O-proj: fp32 transposed [B,D,S]
                int gcol = bn + col;
                float* C = (float*)C0v;
                float bv0 = b0p[gcol], bv1 = b0p[gcol + 1];
                C[((size_t)b * D_ + gcol    ) * S_ + s    ] = c[mt][nt][0] + bv0;
                C[((size_t)b * D_ + gcol + 1) * S_ + s    ] = c[mt][nt][1] + bv1;
                C[((size_t)b * D_ + gcol    ) * S_ + s + 8] = c[mt][nt][2] + bv0;
                C[((size_t)b * D_ + gcol + 1) * S_ + s + 8] = c[mt][nt][3] + bv1;
            }
        }
    }
}

// ---------------------------------------------------------------------------
// 4) Flash attention.  ex2.approx.f16x2 softmax, ones-mma row sums,
//    Q fragments hoisted to registers (loop-invariant; saves 4 ldsm.x4 per
//    tile per warp).
// ---------------------------------------------------------------------------
#define AST 72
#define PST 72
#define ATTN_SMEM_BYTES ((128*AST + 2*64*AST + 2*64*AST + 8*16*PST) * 2)  // 73728

__global__ void __launch_bounds__(256, 2)
flash_attn() {
    extern __shared__ __half sh[];
    __half* Qs = sh;                       // [128][72]
    __half* Ks = Qs + 128 * AST;           // [2][64][72]   [key][d]
    __half* Vs = Ks + 2 * 64 * AST;        // [2][64][72]   [key][d]
    __half* Ps = Vs + 2 * 64 * AST;        // [8][16][72]   per-warp P

    int t = threadIdx.x, w = t >> 5, lane = t & 31;
    int lm = lane >> 2, lk = lane & 3;
    int bh = blockIdx.y;
    int qb = blockIdx.x * 128;
    size_t base = (size_t)bh * S_ * HD_;

    int rowg = t >> 3;   // 0..31
    int chk  = t & 7;    // 0..7
    int l15 = lane & 15;
    int lhi = (lane >> 4) * 8;
    const float L2E = 1.4426950408889634f;
    const uint32_t ONES2 = 0x3C003C00u;          // half2(1,1)
    uint32_t onesb[2] = {ONES2, ONES2};

#pragma unroll
    for (int i = 0; i < 4; i++) {
        int r = rowg + i * 32;
        cpasync16(s2u(&Qs[r * AST + chk * 8]),
                  g_q + base + (size_t)(qb + r) * HD_ + chk * 8);
    }
    cp_commit();

    auto issue = [&](int kt, int p) {
#pragma unroll
        for (int i = 0; i < 2; i++) {
            int r = rowg + i * 32;
            cpasync16(s2u(&Ks[(p * 64 + r) * AST + chk * 8]),
                      g_k + base + (size_t)(kt + r) * HD_ + chk * 8);
            cpasync16(s2u(&Vs[(p * 64 + r) * AST + chk * 8]),
                      g_v + base + (size_t)(kt + r) * HD_ + chk * 8);
        }
        cp_commit();
    };

    issue(0, 0);

    float o[8][4];
#pragma unroll
    for (int nt = 0; nt < 8; nt++)
#pragma unroll
        for (int i = 0; i < 4; i++) o[nt][i] = 0.f;
    float m0 = -INFINITY, m1 = -INFINITY, l0 = 0.f, l1 = 0.f;

    __half* Pw = Ps + w * 16 * PST;
    uint32_t aq[4][4];           // Q fragments, loaded once at it==0

    const int NT = S_ / 64;
    for (int it = 0; it < NT; it++) {
        int p = it & 1;
        cp_wait0();
        __syncthreads();
        if (it == 0) {
#pragma unroll
            for (int ks = 0; ks < 4; ks++)
                ldsm_x4(aq[ks][0], aq[ks][1], aq[ks][2], aq[ks][3],
                        s2u(&Qs[(w * 16 + l15) * AST + ks * 16 + lhi]));
        }
        if (it + 1 < NT) issue((it + 1) * 64, 1 - p);

        const __half* Kb = Ks + p * 64 * AST;
        const __half* Vb = Vs + p * 64 * AST;

        // S = Q K^T
        float sacc[8][4];
#pragma unroll
        for (int nt = 0; nt < 8; nt++)
#pragma unroll
            for (int i = 0; i < 4; i++) sacc[nt][i] = 0.f;

#pragma unroll
        for (int ks = 0; ks < 4; ks++) {
            int kb = ks * 16;
            uint32_t bf[8][2];
#pragma unroll
            for (int j = 0; j < 4; j++) {
                int g = lane >> 3;
                int nrow = (2 * j + (g >> 1)) * 8 + (lane & 7);
                int ncol = kb + (g & 1) * 8;
                ldsm_x4(bf[2*j][0], bf[2*j][1], bf[2*j+1][0], bf[2*j+1][1],
                        s2u(&Kb[nrow * AST + ncol]));
            }
#pragma unroll
            for (int nt = 0; nt < 8; nt++)
                mma_f16(sacc[nt], aq[ks], bf[nt]);
        }

        // Row max (rows lm, lm+8; 4 lanes per row -> xor 1,2)
        float mx0 = -INFINITY, mx1 = -INFINITY;
#pragma unroll
        for (int nt = 0; nt < 8; nt++) {
            mx0 = fmaxf(mx0, fmaxf(sacc[nt][0], sacc[nt][1]));
            mx1 = fmaxf(mx1, fmaxf(sacc[nt][2], sacc[nt][3]));
        }
        mx0 = fmaxf(mx0, __shfl_xor_sync(0xffffffffu, mx0, 1));
        mx0 = fmaxf(mx0, __shfl_xor_sync(0xffffffffu, mx0, 2));
        mx1 = fmaxf(mx1, __shfl_xor_sync(0xffffffffu, mx1, 1));
        mx1 = fmaxf(mx1, __shfl_xor_sync(0xffffffffu, mx1, 2));

        float nm0 = fmaxf(m0, mx0), nm1 = fmaxf(m1, mx1);
        float sc0 = __expf(m0 - nm0), sc1 = __expf(m1 - nm1);
        float bb0 = nm0 * L2E, bb1 = nm1 * L2E;
        m0 = nm0;  m1 = nm1;

        // P = exp2((s-m)*log2e) in f16x2, stored straight to Pw
#pragma unroll
        for (int nt = 0; nt < 8; nt++) {
            float e00 = fmaf(sacc[nt][0], L2E, -bb0);
            float e01 = fmaf(sacc[nt][1], L2E, -bb0);
            float e10 = fmaf(sacc[nt][2], L2E, -bb1);
            float e11 = fmaf(sacc[nt][3], L2E, -bb1);
            int kc = nt * 8 + 2 * lk;
            *(uint32_t*)&Pw[(lm    ) * PST + kc] = exp2_f16x2(e00, e01);
            *(uint32_t*)&Pw[(lm + 8) * PST + kc] = exp2_f16x2(e10, e11);
        }

#pragma unroll
        for (int nt = 0; nt < 8; nt++) {
            o[nt][0] *= sc0; o[nt][1] *= sc0;
            o[nt][2] *= sc1; o[nt][3] *= sc1;
        }
        __syncwarp();

        // O += P V ; row-sum of P via ones-B mma (tensor pipe, exact fp32)
        float lacc[4] = {0.f, 0.f, 0.f, 0.f};
#pragma unroll
        for (int ks = 0; ks < 4; ks++) {
            int kb = ks * 16;
            uint32_t a[4];
            ldsm_x4(a[0], a[1], a[2], a[3],
                    s2u(&Pw[l15 * PST + kb + lhi]));
            mma_f16(lacc, a, onesb);
#pragma unroll
            for (int j = 0; j < 4; j++) {
                uint32_t b0, b1, b2, b3;
                int vrow = kb + l15;
                int vcol = (2 * j) * 8 + lhi;
                ldsm_x4_t(b0, b1, b2, b3, s2u(&Vb[vrow * AST + vcol]));
                uint32_t bb0v[2] = {b0, b1};
                uint32_t bb1v[2] = {b2, b3};
                mma_f16(o[2*j    ], a, bb0v);
                mma_f16(o[2*j + 1], a, bb1v);
            }
        }
        l0 = l0 * sc0 + lacc[0];
        l1 = l1 * sc1 + lacc[2];
        __syncwarp();
    }

    // Epilogue: normalize, write ctx[B,S,D] fp16
    float inv0 = 1.f / l0, inv1 = 1.f / l1;
    int b = bh / H_, h = bh - b * H_;
    int srow = qb + w * 16 + lm;
#pragma unroll
    for (int nt = 0; nt < 8; nt++) {
        int col = h * HD_ + nt * 8 + 2 * lk;
        __half2* p0 = (__half2*)&g_ctx[((size_t)b * S_ + srow    ) * D_ + col];
        __half2* p1 = (__half2*)&g_ctx[((size_t)b * S_ + srow + 8) * D_ + col];
        *p0 = __floats2half2_rn(o[nt][0] * inv0, o[nt][1] * inv0);
        *p1 = __floats2half2_rn(o[nt][2] * inv1, o[nt][3] * inv1);
    }
}

// ---------------------------------------------------------------------------
// Launch
// ---------------------------------------------------------------------------
extern "C" void kernel_launch(void* const* d_in, const int* in_sizes, int n_in,
                              void* d_out, int out_size) {
    (void)in_sizes; (void)n_in; (void)out_size;
    const float* x  = (const float*)d_in[0];
    const float* Wq = (const float*)d_in[1];
    const float* bq = (const float*)d_in[2];
    const float* Wk = (const float*)d_in[3];
    const float* bk = (const float*)d_in[4];
    const float* Wv = (const float*)d_in[5];
    const float* bv = (const float*)d_in[6];
    const float* Wo = (const float*)d_in[7];
    const float* bo = (const float*)d_in[8];
    float* out = (float*)d_out;

    __half *xt, *q, *k, *v, *ctx, *wqkv, *wo;
    cudaGetSymbolAddress((void**)&xt,   g_xt);
    cudaGetSymbolAddress((void**)&q,    g_q);
    cudaGetSymbolAddress((void**)&k,    g_k);
    cudaGetSymbolAddress((void**)&v,    g_v);
    cudaGetSymbolAddress((void**)&ctx,  g_ctx);
    cudaGetSymbolAddress((void**)&wqkv, g_wqkv);
    cudaGetSymbolAddress((void**)&wo,   g_wo);

    cudaFuncSetAttribute(gemm_f16<1>, cudaFuncAttributeMaxDynamicSharedMemorySize,
                         GEMM_SMEM);
    cudaFuncSetAttribute(gemm_f16<2>, cudaFuncAttributeMaxDynamicSharedMemorySize,
                         GEMM_SMEM);
    cudaFuncSetAttribute(flash_attn, cudaFuncAttributeMaxDynamicSharedMemorySize,
                         ATTN_SMEM_BYTES);

    // 0) weights -> fp16 scratch
    weight_prep<<<(D_ * D_ / 4 + 255) / 256, 256>>>(Wq, Wk, Wv, Wo);
    // 1) x + PE -> xt[B,S,D] fp16 (PE inline)
    addpe_transpose<<<dim3(S_ / 32, D_ / 32, B_), dim3(32, 8)>>>(x);
    // 2) fused QKV projection (N=3072) -> q,k,v all [BH][S][hd] fp16
    gemm_f16<1><<<dim3(3 * D_ / 128, BS_ / 128), 256, GEMM_SMEM>>>(
        xt, wqkv, bq, bk, bv, q, k, v, D_);
    // 3) attention -> ctx[B,S,D] fp16
    flash_attn<<<dim3(S_ / 128, B_ * H_), 256, ATTN_SMEM_BYTES>>>();
    // 4) output projection -> [B,D,S] fp32
    gemm_f16<2><<<dim3(D_ / 128, BS_ / 128), 256, GEMM_SMEM>>>(
        ctx, wo, bo, nullptr, nullptr, out, nullptr, nullptr, D_);
}